// round 10
// baseline (speedup 1.0000x reference)
#include <cuda_runtime.h>
#include <cstdint>

#define L    768
#define D    256
#define NT   12
#define SPAN 8
#define NCTA 384

// ---------------- device scratch (static, no allocs) ----------------
__device__ __align__(16) float g_ht[8][L * D];        // ht per span-length diagonal
__device__ __align__(16) float g_BsL[1024 * 256];     // stacked interleaved [Wl|Gl], col'=4d+j
__device__ __align__(16) float g_BsR[1024 * 256];     // stacked interleaved [Wr|Gr]
__device__ __align__(16) float g_biasS[1024];         // stacked bias
__device__ __align__(16) float g_tagsc[8][L * NT];    // tag scores per diagonal (for gold)
__device__ __align__(16) float g_ex[L * NT * SPAN];   // exp(span scores) [i][t2][k]
__device__ __align__(16) float g_GT[11 * 96 * 96];    // chunk transfer matrices [c][j][o]
__device__ __align__(16) float g_sc[12 * 96];         // per-column log scales
__device__ __align__(16) float g_R[96 * 12];          // last chunk: A_767 rows [j][t2]
__device__ unsigned g_cnt;                            // grid barrier state (zero-init)
__device__ unsigned g_gen;

#define F2U(x) __float_as_uint(x)

__device__ __forceinline__ void mma_tf32(float& c0, float& c1, float& c2, float& c3,
                                         uint32_t a0, uint32_t a1, uint32_t a2, uint32_t a3,
                                         uint32_t b0, uint32_t b1)
{
    asm volatile("mma.sync.aligned.m16n8k8.row.col.f32.tf32.tf32.f32 "
                 "{%0,%1,%2,%3}, {%4,%5,%6,%7}, {%8,%9}, {%0,%1,%2,%3};\n"
                 : "+f"(c0), "+f"(c1), "+f"(c2), "+f"(c3)
                 : "r"(a0), "r"(a1), "r"(a2), "r"(a3), "r"(b0), "r"(b1));
}

__device__ __forceinline__ void cpa16(float* dst, const float* src)
{
    uint32_t d = (uint32_t)__cvta_generic_to_shared(dst);
    asm volatile("cp.async.cg.shared.global [%0], [%1], 16;\n" :: "r"(d), "l"(src));
}
#define CP_COMMIT() asm volatile("cp.async.commit_group;\n")
#define CP_WAIT(n)  asm volatile("cp.async.wait_group %0;\n" :: "n"(n))

// ---------------- software grid barrier (all NCTA co-resident by launch_bounds) ----
__device__ __forceinline__ void grid_bar()
{
    __syncthreads();
    if (threadIdx.x == 0) {
        __threadfence();
        unsigned gen = *(volatile unsigned*)&g_gen;
        if (atomicAdd(&g_cnt, 1u) == NCTA - 1u) {
            g_cnt = 0u;
            __threadfence();
            atomicAdd(&g_gen, 1u);
        } else {
            while (*(volatile unsigned*)&g_gen == gen) __nanosleep(32);
        }
        __threadfence();
    }
    __syncthreads();
}

// ---------------- shared pool ----------------
// dual phase (BK=16, 3-stage, stride 24): DA(s)=s*1560 (65x24); DB(s,h)=4680+s*1536+h*768
// h    phase (BK=32, 2-stage, stride 40): HA(s)=s*2560 (64x40); HB(s)=5120+s*1280
#define POOL_FLOATS 9288
#define DA_OFF(s)    ((s) * 1560)
#define DB_OFF(s, h) (4680 + (s) * 1536 + (h) * 768)
#define HA_OFF(s)    ((s) * 2560)
#define HB_OFF(s)    (5120 + (s) * 1280)

// ================== persistent mega kernel ==================
__global__ void __launch_bounds__(256, 3) mega_kernel(
    const float* __restrict__ feats, const float* __restrict__ Wd,
    const float* __restrict__ bd,
    const float* __restrict__ Wl, const float* __restrict__ Wr,
    const float* __restrict__ Gl, const float* __restrict__ Gr,
    const float* __restrict__ bl, const float* __restrict__ br,
    const float* __restrict__ bgl, const float* __restrict__ bgr,
    const float* __restrict__ Wt, const float* __restrict__ bt,
    const float* __restrict__ trans, const int* __restrict__ tags,
    float* __restrict__ out)
{
    __shared__ __align__(16) float pool[POOL_FLOATS];
    const int cta = blockIdx.x;
    const int tid = threadIdx.x;
    const int lane = tid & 31, warp = tid >> 5;
    const int g = lane >> 2, c = lane & 3;

    // ================= phase 0a: prep stacked weights + zero g_ex =================
    {
        int idx = cta * 256 + tid;
        if (idx < 65536) {
            int row = idx >> 6, k = (idx & 63) * 4;
            int d = row >> 2, j = row & 3;
            int srcrow = (j == 0) ? d : ((j - 1) * 256 + d);
            const float* sl4 = (j == 0) ? Wl : Gl;
            const float* sr4 = (j == 0) ? Wr : Gr;
            *(float4*)&g_BsL[(size_t)row * 256 + k] = *(const float4*)&sl4[(size_t)srcrow * 256 + k];
            *(float4*)&g_BsR[(size_t)row * 256 + k] = *(const float4*)&sr4[(size_t)srcrow * 256 + k];
        }
        if (idx < 1024) {
            int dd = idx >> 2, jj = idx & 3;
            g_biasS[idx] = (jj == 0) ? (bl[dd] + br[dd])
                                     : (bgl[(jj - 1) * 256 + dd] + bgr[(jj - 1) * 256 + dd]);
        }
        if (idx < L * NT * SPAN) g_ex[idx] = 0.f;
    }

    // ================= phase 0b: h = feats @ Wd^T + bd  (96 CTAs, BK=32, 2-stage) =
    if (cta < 96) {
        const int K = 512, NSTEP = 16;
        const int wm = warp & 3, wn = warp >> 2;
        const int m0 = (cta >> 3) * 64, n0 = (cta & 7) * 32;
        const int ar0 = tid >> 3,          ac0 = (tid & 7) * 4;
        const int ar1 = (tid + 256) >> 3,  ac1 = ((tid + 256) & 7) * 4;
        const int brr = tid >> 3, bcc = (tid & 7) * 4;
        float acc[2][4] = {};

        cpa16(&pool[HA_OFF(0) + ar0 * 40 + ac0], &feats[(size_t)(m0 + ar0) * K + ac0]);
        cpa16(&pool[HA_OFF(0) + ar1 * 40 + ac1], &feats[(size_t)(m0 + ar1) * K + ac1]);
        cpa16(&pool[HB_OFF(0) + brr * 40 + bcc], &Wd[(size_t)(n0 + brr) * K + bcc]);
        CP_COMMIT();

#pragma unroll
        for (int step = 0; step < NSTEP; step++) {
            const int s = step & 1;
            CP_WAIT(0);
            __syncthreads();
            if (step + 1 < NSTEP) {
                const int k0 = (step + 1) * 32, s2 = s ^ 1;
                cpa16(&pool[HA_OFF(s2) + ar0 * 40 + ac0], &feats[(size_t)(m0 + ar0) * K + k0 + ac0]);
                cpa16(&pool[HA_OFF(s2) + ar1 * 40 + ac1], &feats[(size_t)(m0 + ar1) * K + k0 + ac1]);
                cpa16(&pool[HB_OFF(s2) + brr * 40 + bcc], &Wd[(size_t)(n0 + brr) * K + k0 + bcc]);
                CP_COMMIT();
            }
#pragma unroll
            for (int kc = 0; kc < 4; kc++) {
                const int ko = kc * 8 + 2 * c;
                const float* p = &pool[HA_OFF(s) + (wm * 16 + g) * 40 + ko];
                float2 fa0 = *(const float2*)p;
                float2 fa1 = *(const float2*)(p + 8 * 40);
#pragma unroll
                for (int ni = 0; ni < 2; ni++) {
                    const float* pb = &pool[HB_OFF(s) + (wn * 16 + ni * 8 + g) * 40 + ko];
                    float2 fb = *(const float2*)pb;
                    mma_tf32(acc[ni][0], acc[ni][1], acc[ni][2], acc[ni][3],
                             F2U(fa0.x), F2U(fa1.x), F2U(fa0.y), F2U(fa1.y),
                             F2U(fb.x), F2U(fb.y));
                }
            }
        }
#pragma unroll
        for (int ni = 0; ni < 2; ni++) {
            int col = n0 + wn * 16 + ni * 8 + 2 * c;
            float bv0 = bd[col], bv1 = bd[col + 1];
            int row0 = m0 + wm * 16 + g;
            g_ht[0][(size_t)row0 * 256 + col]           = acc[ni][0] + bv0;
            g_ht[0][(size_t)row0 * 256 + col + 1]       = acc[ni][1] + bv1;
            g_ht[0][(size_t)(row0 + 8) * 256 + col]     = acc[ni][2] + bv0;
            g_ht[0][(size_t)(row0 + 8) * 256 + col + 1] = acc[ni][3] + bv1;
        }
    }

    grid_bar();

    // ========== phase 1..7: fused dual GEMM + gate (BK=16, 3-stage, unrolled) =====
    {
        const int wm = warp & 3, wn = warp >> 2;
        const int m0 = (cta >> 5) * 64, n0 = (cta & 31) * 32;
        // A: 260 f4 chunks (65 rows x 4 f4): tid, plus tid<4 -> row 64
        const int ar = tid >> 2, ac4 = (tid & 3) * 4;
        // B: half bh, 128 chunks (32 rows x 4 f4)
        const int bh = tid >> 7, bi = tid & 127;
        const int brr = bi >> 2, bc4 = (bi & 3) * 4;
        const float* bsrc = (bh ? g_BsR : g_BsL) + (size_t)n0 * 256;
        const int NSTEP = 16;

        for (int sl = 1; sl <= 7; sl++) {
            const int M = L - sl;
            const float* Aht = g_ht[sl - 1];
            float* htout = g_ht[sl];
            float acc[2][4] = {};

            // prologue: stages 0,1
#pragma unroll
            for (int st = 0; st < 2; st++) {
                const int k0 = st * 16;
                cpa16(&pool[DA_OFF(st) + ar * 24 + ac4], &Aht[(size_t)(m0 + ar) * 256 + k0 + ac4]);
                if (tid < 4) cpa16(&pool[DA_OFF(st) + 64 * 24 + tid * 4],
                                   &Aht[(size_t)(m0 + 64) * 256 + k0 + tid * 4]);
                cpa16(&pool[DB_OFF(st, bh) + brr * 24 + bc4], &bsrc[(size_t)brr * 256 + k0 + bc4]);
                CP_COMMIT();
            }

#pragma unroll
            for (int step = 0; step < NSTEP; step++) {
                const int s = step % 3;
                if (step + 2 < NSTEP) {
                    CP_WAIT(1);
                    __syncthreads();
                    const int k0 = (step + 2) * 16, s2 = (step + 2) % 3;
                    cpa16(&pool[DA_OFF(s2) + ar * 24 + ac4],
                          &Aht[(size_t)(m0 + ar) * 256 + k0 + ac4]);
                    if (tid < 4) cpa16(&pool[DA_OFF(s2) + 64 * 24 + tid * 4],
                                       &Aht[(size_t)(m0 + 64) * 256 + k0 + tid * 4]);
                    cpa16(&pool[DB_OFF(s2, bh) + brr * 24 + bc4],
                          &bsrc[(size_t)brr * 256 + k0 + bc4]);
                    CP_COMMIT();
                } else {
                    CP_WAIT(0);
                    __syncthreads();
                }
#pragma unroll
                for (int kc = 0; kc < 2; kc++) {
                    const int ko = kc * 8 + 2 * c;
                    const float* p = &pool[DA_OFF(s) + (wm * 16 + g) * 24 + ko];
                    float2 fa0 = *(const float2*)p;
                    float2 fa1 = *(const float2*)(p + 8 * 24);
                    float2 fr0 = *(const float2*)(p + 24);       // shifted one row: r
                    float2 fr1 = *(const float2*)(p + 9 * 24);
#pragma unroll
                    for (int ni = 0; ni < 2; ni++) {
                        const int boff = (wn * 16 + ni * 8 + g) * 24 + ko;
                        float2 fbl = *(const float2*)&pool[DB_OFF(s, 0) + boff];
                        float2 fbr = *(const float2*)&pool[DB_OFF(s, 1) + boff];
                        mma_tf32(acc[ni][0], acc[ni][1], acc[ni][2], acc[ni][3],
                                 F2U(fa0.x), F2U(fa1.x), F2U(fa0.y), F2U(fa1.y),
                                 F2U(fbl.x), F2U(fbl.y));
                        mma_tf32(acc[ni][0], acc[ni][1], acc[ni][2], acc[ni][3],
                                 F2U(fr0.x), F2U(fr1.x), F2U(fr0.y), F2U(fr1.y),
                                 F2U(fbr.x), F2U(fbr.y));
                    }
                }
            }
            // ---- fused gate epilogue ----
#pragma unroll
            for (int ni = 0; ni < 2; ni++) {
                int colb = n0 + wn * 16 + ni * 8 + 2 * c;
                float b0 = g_biasS[colb], b1 = g_biasS[colb + 1];
                float z00 = acc[ni][0] + b0, z01 = acc[ni][1] + b1;
                float z10 = acc[ni][2] + b0, z11 = acc[ni][3] + b1;
                float w00 = __shfl_xor_sync(0xffffffffu, z00, 1);
                float w01 = __shfl_xor_sync(0xffffffffu, z01, 1);
                float w10 = __shfl_xor_sync(0xffffffffu, z10, 1);
                float w11 = __shfl_xor_sync(0xffffffffu, z11, 1);
                if ((c & 1) == 0) {
                    int d = colb >> 2;
                    int row0 = m0 + wm * 16 + g;
#pragma unroll
                    for (int rr = 0; rr < 2; rr++) {
                        int row = row0 + rr * 8;
                        if (row < M) {
                            float zh  = rr ? z10 : z00;
                            float zg0 = rr ? z11 : z01;
                            float zg1 = rr ? w10 : w00;
                            float zg2 = rr ? w11 : w01;
                            float lft = Aht[(size_t)row * 256 + d];
                            float rgt = Aht[(size_t)(row + 1) * 256 + d];
                            float hh = 4.f / (1.f + __expf(-zh)) - 2.f;
                            float mx = fmaxf(zg0, fmaxf(zg1, zg2));
                            float e0 = __expf(zg0 - mx), e1 = __expf(zg1 - mx),
                                  e2 = __expf(zg2 - mx);
                            float inv = 1.f / (e0 + e1 + e2);
                            htout[(size_t)row * 256 + d] =
                                (e0 * hh + e1 * lft + e2 * rgt) * inv;
                        }
                    }
                }
            }
            grid_bar();
        }
    }

    // ================= phase 8: tag scores + exp gather =================
    {
        for (int i = tid; i < NT * D; i += 256) pool[i] = Wt[i];
        __syncthreads();
#pragma unroll
        for (int rep = 0; rep < 2; rep++) {
            int gw = cta * 8 + warp + rep * 3072;
            int sl = gw / L;
            int pos = gw - sl * L;
            if (pos + sl < L) {
                const float* hp = g_ht[sl] + (size_t)pos * D;
                float4 h0 = *(const float4*)&hp[lane * 8];
                float4 h1 = *(const float4*)&hp[lane * 8 + 4];
                float hv[8] = {h0.x,h0.y,h0.z,h0.w,h1.x,h1.y,h1.z,h1.w};
                int i_end = pos + sl, kk = 7 - sl;
#pragma unroll
                for (int t = 0; t < NT; t++) {
                    const float* wp = &pool[t * D + lane * 8];
                    float4 w0 = *(const float4*)wp;
                    float4 w1 = *(const float4*)(wp + 4);
                    float s = hv[0]*w0.x + hv[1]*w0.y + hv[2]*w0.z + hv[3]*w0.w
                            + hv[4]*w1.x + hv[5]*w1.y + hv[6]*w1.z + hv[7]*w1.w;
#pragma unroll
                    for (int o = 16; o; o >>= 1) s += __shfl_xor_sync(0xffffffffu, s, o);
                    if (lane == 0) {
                        float val = s + bt[t];
                        g_tagsc[sl][pos * NT + t] = val;
                        g_ex[((size_t)i_end * NT + t) * SPAN + kk] = __expf(val);
                    }
                }
            }
        }
    }

    grid_bar();

    // ================= phase 9: chunk transfer matrices (basis runs) =================
    if (warp < 3) {
        const int run = cta * 3 + warp;            // 0..1151
        const int chunk = run / 96, j = run - chunk * 96;
        const int slotj = j / 12, tj = j - slotj * 12;
        const int t2 = (lane < 12) ? lane : 11;

        float eTc[12];
#pragma unroll
        for (int t1 = 0; t1 < 12; t1++) eTc[t1] = __expf(trans[t1 * 12 + t2]);

        float Cw[8];
#pragma unroll
        for (int k = 0; k < 8; k++) Cw[k] = 0.f;
        if (lane == tj) Cw[slotj] = 1.f;
        float sc = 0.f;
        float lastA = 0.f;

        const float4* exb = (const float4*)(g_ex + ((size_t)(chunk * 64) * 12 + t2) * 8);
        float4 c0 = exb[0], c1 = exb[1];
        float4 n0 = exb[24], n1 = exb[25];

        for (int blk = 0; blk < 8; blk++) {
#pragma unroll
            for (int u = 0; u < 8; u++) {
                const int li = blk * 8 + u;
                float4 f0 = c0, f1 = c1;
                c0 = n0; c1 = n1;
                if (li + 2 < 64) {
                    n0 = exb[(li + 2) * 24];
                    n1 = exb[(li + 2) * 24 + 1];
                }
                float e0=f0.x,e1=f0.y,e2=f0.z,e3=f0.w,e4=f1.x,e5=f1.y,e6=f1.z,e7=f1.w;
                float v01 = fmaf(e1, Cw[(u + 1) & 7], e0 * Cw[(u + 0) & 7]);
                float v23 = fmaf(e3, Cw[(u + 3) & 7], e2 * Cw[(u + 2) & 7]);
                float v45 = fmaf(e5, Cw[(u + 5) & 7], e4 * Cw[(u + 4) & 7]);
                float v6  = e6 * Cw[(u + 6) & 7];
                float A = fmaf(e7, Cw[(u + 7) & 7], (v01 + v23) + (v45 + v6));
                lastA = A;
                float bnA = 0.f, bnB = 0.f;
#pragma unroll
                for (int t1 = 0; t1 < 6; t1++) {
                    bnA = fmaf(eTc[t1],     __shfl_sync(0xffffffffu, A, t1),     bnA);
                    bnB = fmaf(eTc[t1 + 6], __shfl_sync(0xffffffffu, A, t1 + 6), bnB);
                }
                Cw[u] = bnA + bnB;
            }
            if (blk != 7) {
                float m = (lane < 12) ? Cw[7] : 0.f;
#pragma unroll
                for (int o = 16; o; o >>= 1) m = fmaxf(m, __shfl_xor_sync(0xffffffffu, m, o));
                if (m < 1e-30f) m = 1.f;
                float inv = 1.f / m;
#pragma unroll
                for (int k = 0; k < 8; k++) Cw[k] *= inv;
                sc += __logf(m);
            }
        }

        if (chunk < 11) {
            if (lane < 12) {
#pragma unroll
                for (int slot = 0; slot < 8; slot++)
                    g_GT[((size_t)chunk * 96 + j) * 96 + slot * 12 + lane] = Cw[slot];
            }
            if (lane == 0) g_sc[chunk * 96 + j] = sc;
        } else {
            if (lane < 12) g_R[j * 12 + lane] = lastA;
            if (lane == 0) g_sc[11 * 96 + j] = sc;
        }
    }

    grid_bar();
    if (cta != 0) return;

    // ================= phase 10 (CTA 0 only): gold + chunk matvec chain =================
    {
        float* s_sh   = pool;            // 96
        float* st_sh  = pool + 96;       // 96
        float* lv     = pool + 192;      // 11
        float* wred   = pool + 204;      // 3
        float* wred2  = pool + 208;      // 3
        float* gold_sh= pool + 212;      // 1
        float* scall  = pool + 256;      // 1152
        float* Rsh    = pool + 1472;     // 1152
        float* part   = pool + 2688;     // 768

        __syncthreads();
        for (int i = tid; i < 1152; i += 256) { scall[i] = g_sc[i]; Rsh[i] = g_R[i]; }

        if (warp == 0) {
            float gold = 0.f;
            for (int s = lane; s < 96; s += 32) {
                int i  = tags[s * 4 + 0];
                int j  = tags[s * 4 + 1];
                int pr = tags[s * 4 + 2];
                int t  = tags[s * 4 + 3];
                int sl = j - i;
                float base = (sl >= 0 && sl < SPAN && i >= 0 && i + sl < L)
                           ? g_tagsc[sl][i * NT + t] : bt[t];
                gold += base + trans[pr * NT + t];
            }
#pragma unroll
            for (int o = 16; o; o >>= 1) gold += __shfl_xor_sync(0xffffffffu, gold, o);
            if (lane == 0) gold_sh[0] = gold;
        }
        if (tid < 96) s_sh[tid] = (tid >= 84) ? expf(trans[10 * 12 + (tid - 84)]) : 0.f;
        __syncthreads();

        const int p8 = warp;
        float Sacc = 0.f, mc = 0.f;
        for (int cch = 0; cch < 12; cch++) {
            float m = (tid < 96) ? scall[cch * 96 + tid] : -3e38f;
#pragma unroll
            for (int off = 16; off; off >>= 1) m = fmaxf(m, __shfl_xor_sync(0xffffffffu, m, off));
            if (tid < 96 && lane == 0) wred[warp] = m;
            __syncthreads();
            mc = fmaxf(fmaxf(wred[0], wred[1]), wred[2]);
            if (tid < 96) st_sh[tid] = s_sh[tid] * expf(scall[cch * 96 + tid] - mc);
            __syncthreads();

            if (cch < 11) {
                const float* G = g_GT + (size_t)cch * 9216 + (size_t)(p8 * 12) * 96;
                const float* sv = &st_sh[p8 * 12];
                float a0 = 0.f, a1 = 0.f, a2 = 0.f;
#pragma unroll
                for (int j = 0; j < 12; j++) {
                    float svj = sv[j];
                    a0 = fmaf(G[j * 96 + lane],      svj, a0);
                    a1 = fmaf(G[j * 96 + lane + 32], svj, a1);
                    a2 = fmaf(G[j * 96 + lane + 64], svj, a2);
                }
                part[p8 * 96 + lane]      = a0;
                part[p8 * 96 + lane + 32] = a1;
                part[p8 * 96 + lane + 64] = a2;
                __syncthreads();
                float snew = 0.f;
                if (tid < 96) {
                    snew = ((part[tid] + part[96 + tid]) + (part[192 + tid] + part[288 + tid]))
                         + ((part[384 + tid] + part[480 + tid]) + (part[576 + tid] + part[672 + tid]));
                }
                float m2 = (tid < 96) ? snew : 0.f;
#pragma unroll
                for (int off = 16; off; off >>= 1) m2 = fmaxf(m2, __shfl_xor_sync(0xffffffffu, m2, off));
                if (tid < 96 && lane == 0) wred2[warp] = m2;
                __syncthreads();
                float mx = fmaxf(fmaxf(wred2[0], wred2[1]), wred2[2]);
                if (mx < 1e-30f) mx = 1.f;
                if (tid < 96) s_sh[tid] = snew / mx;
                Sacc += mc + logf(mx);
                __syncthreads();
            }
        }

        if (tid < 11) {
            float a0 = 0.f, a1 = 0.f, a2 = 0.f, a3 = 0.f;
#pragma unroll 4
            for (int j = 0; j < 96; j += 4) {
                a0 = fmaf(Rsh[(j + 0) * 12 + tid], st_sh[j + 0], a0);
                a1 = fmaf(Rsh[(j + 1) * 12 + tid], st_sh[j + 1], a1);
                a2 = fmaf(Rsh[(j + 2) * 12 + tid], st_sh[j + 2], a2);
                a3 = fmaf(Rsh[(j + 3) * 12 + tid], st_sh[j + 3], a3);
            }
            lv[tid] = logf((a0 + a1) + (a2 + a3));
        }
        __syncthreads();
        if (tid == 0) {
            float logZ = 11.f * (Sacc + mc);
            for (int t = 0; t < 11; t++) logZ += lv[t];
            out[0] = logZ - gold_sh[0];
        }
    }
}

// ---------------- launch ----------------
extern "C" void kernel_launch(void* const* d_in, const int* in_sizes, int n_in,
                              void* d_out, int out_size)
{
    const float* feats = (const float*)d_in[0];
    const int*   tags  = (const int*)d_in[1];
    const float* Wd    = (const float*)d_in[2];
    const float* bd    = (const float*)d_in[3];
    const float* Wl    = (const float*)d_in[4];
    const float* bl    = (const float*)d_in[5];
    const float* Wr    = (const float*)d_in[6];
    const float* br    = (const float*)d_in[7];
    const float* Gl    = (const float*)d_in[8];
    const float* bgl   = (const float*)d_in[9];
    const float* Gr    = (const float*)d_in[10];
    const float* bgr   = (const float*)d_in[11];
    const float* Wt    = (const float*)d_in[12];
    const float* bt    = (const float*)d_in[13];
    const float* trans = (const float*)d_in[14];
    float* out = (float*)d_out;

    mega_kernel<<<NCTA, 256>>>(feats, Wd, bd, Wl, Wr, Gl, Gr,
                               bl, br, bgl, bgr, Wt, bt, trans, tags, out);
}

// round 11
// speedup vs baseline: 1.1211x; 1.1211x over previous
#include <cuda_runtime.h>
#include <cstdint>

#define L    768
#define D    256
#define NT   12
#define SPAN 8
#define NCTA 128
#define NTHR 384

// ---------------- device scratch (static, no allocs) ----------------
__device__ __align__(16) float g_ht[8][L * D];        // ht per span-length diagonal
__device__ __align__(16) float g_biasS[1024];         // stacked bias
__device__ __align__(16) float g_tagsc[8][L * NT];    // tag scores per diagonal (for gold)
__device__ __align__(16) float g_ex[L * NT * SPAN];   // exp(span scores) [i][t2][k]
__device__ __align__(16) float g_GT[11 * 96 * 96];    // chunk transfer matrices [c][j][o]
__device__ __align__(16) float g_sc[12 * 96];         // per-column log scales
__device__ __align__(16) float g_R[96 * 12];          // last chunk: A_767 rows [j][t2]
__device__ unsigned g_cnt;                            // grid barrier state (zero-init)
__device__ unsigned g_gen;

#define F2U(x) __float_as_uint(x)

__device__ __forceinline__ void mma_tf32(float& c0, float& c1, float& c2, float& c3,
                                         uint32_t a0, uint32_t a1, uint32_t a2, uint32_t a3,
                                         uint32_t b0, uint32_t b1)
{
    asm volatile("mma.sync.aligned.m16n8k8.row.col.f32.tf32.tf32.f32 "
                 "{%0,%1,%2,%3}, {%4,%5,%6,%7}, {%8,%9}, {%0,%1,%2,%3};\n"
                 : "+f"(c0), "+f"(c1), "+f"(c2), "+f"(c3)
                 : "r"(a0), "r"(a1), "r"(a2), "r"(a3), "r"(b0), "r"(b1));
}

__device__ __forceinline__ void cpa16(float* dst, const float* src)
{
    uint32_t d = (uint32_t)__cvta_generic_to_shared(dst);
    asm volatile("cp.async.cg.shared.global [%0], [%1], 16;\n" :: "r"(d), "l"(src));
}
#define CP_COMMIT() asm volatile("cp.async.commit_group;\n")
#define CP_WAIT(n)  asm volatile("cp.async.wait_group %0;\n" :: "n"(n))

// ---------------- software grid barrier (128 CTAs, 1/SM guaranteed) ----------------
__device__ __forceinline__ void grid_bar()
{
    __syncthreads();
    if (threadIdx.x == 0) {
        __threadfence();
        unsigned gen = *(volatile unsigned*)&g_gen;
        if (atomicAdd(&g_cnt, 1u) == NCTA - 1u) {
            g_cnt = 0u;
            __threadfence();
            atomicAdd(&g_gen, 1u);
        } else {
            while (*(volatile unsigned*)&g_gen == gen) __nanosleep(32);
        }
        __threadfence();
    }
    __syncthreads();
}

// ---------------- dynamic shared pool layout (floats) ----------------
// B resident : BR[half][64 rows][stride 264]  at 0        (2*64*264 = 33792)
// dual A     : DA(s) = 33792 + s*3880         (97 rows x stride 40, 2 stages)
// h aliases  : HA(s) = 33792 + s*1920 ; HB(s) = 33792+3840 + s*1280
#define BR_HALF     16896
#define SB          264
#define DA_OFF(s)   (33792 + (s) * 3880)
#define HA_OFF(s)   (33792 + (s) * 1920)
#define HB_OFF(s)   (33792 + 3840 + (s) * 1280)
#define POOL_FLOATS 41552
#define SMEM_BYTES  (POOL_FLOATS * 4)

// ================== persistent mega kernel ==================
__global__ void __launch_bounds__(NTHR, 1) mega_kernel(
    const float* __restrict__ feats, const float* __restrict__ Wd,
    const float* __restrict__ bd,
    const float* __restrict__ Wl, const float* __restrict__ Wr,
    const float* __restrict__ Gl, const float* __restrict__ Gr,
    const float* __restrict__ bl, const float* __restrict__ br,
    const float* __restrict__ bgl, const float* __restrict__ bgr,
    const float* __restrict__ Wt, const float* __restrict__ bt,
    const float* __restrict__ trans, const int* __restrict__ tags,
    float* __restrict__ out)
{
    extern __shared__ __align__(16) float pool[];
    const int cta = blockIdx.x;
    const int tid = threadIdx.x;
    const int lane = tid & 31, warp = tid >> 5;
    const int g = lane >> 2, c = lane & 3;

    // ================= phase 0a: zero g_ex, build g_biasS =================
    for (int i = cta * NTHR + tid; i < L * NT * SPAN; i += NCTA * NTHR) g_ex[i] = 0.f;
    if (cta == 0) {
        for (int i = tid; i < 1024; i += NTHR) {
            int dd = i >> 2, jj = i & 3;
            g_biasS[i] = (jj == 0) ? (bl[dd] + br[dd])
                                   : (bgl[(jj - 1) * 256 + dd] + bgr[(jj - 1) * 256 + dd]);
        }
    }

    // ================= phase 0b: h = feats @ Wd^T + bd  (BM=48, BN=32, all CTAs) ===
    {
        const int m0h = (cta >> 3) * 48, n0h = (cta & 7) * 32;
        const int wmh = warp >> 2, wnh = warp & 3;       // 0..2, 0..3
        const int har = tid >> 3, hac = (tid & 7) * 4;   // 384 A f4 chunks
        const bool do_b = tid < 256;
        float acch[4] = {};

        cpa16(&pool[HA_OFF(0) + har * 40 + hac], &feats[(size_t)(m0h + har) * 512 + hac]);
        if (do_b) cpa16(&pool[HB_OFF(0) + har * 40 + hac], &Wd[(size_t)(n0h + har) * 512 + hac]);
        CP_COMMIT();

#pragma unroll
        for (int step = 0; step < 16; step++) {
            const int s = step & 1;
            CP_WAIT(0);
            __syncthreads();
            if (step + 1 < 16) {
                const int k0 = (step + 1) * 32, s2 = s ^ 1;
                cpa16(&pool[HA_OFF(s2) + har * 40 + hac],
                      &feats[(size_t)(m0h + har) * 512 + k0 + hac]);
                if (do_b) cpa16(&pool[HB_OFF(s2) + har * 40 + hac],
                                &Wd[(size_t)(n0h + har) * 512 + k0 + hac]);
                CP_COMMIT();
            }
#pragma unroll
            for (int kc = 0; kc < 4; kc++) {
                const int ko = kc * 8 + 2 * c;
                const float* p = &pool[HA_OFF(s) + (wmh * 16 + g) * 40 + ko];
                float2 fa0 = *(const float2*)p;
                float2 fa1 = *(const float2*)(p + 8 * 40);
                const float* pb = &pool[HB_OFF(s) + (wnh * 8 + g) * 40 + ko];
                float2 fb = *(const float2*)pb;
                mma_tf32(acch[0], acch[1], acch[2], acch[3],
                         F2U(fa0.x), F2U(fa1.x), F2U(fa0.y), F2U(fa1.y),
                         F2U(fb.x), F2U(fb.y));
            }
        }
        {
            int col = n0h + wnh * 8 + 2 * c;
            int row0 = m0h + wmh * 16 + g;
            g_ht[0][(size_t)row0 * 256 + col]           = acch[0] + bd[col];
            g_ht[0][(size_t)row0 * 256 + col + 1]       = acch[1] + bd[col + 1];
            g_ht[0][(size_t)(row0 + 8) * 256 + col]     = acch[2] + bd[col];
            g_ht[0][(size_t)(row0 + 8) * 256 + col + 1] = acch[3] + bd[col + 1];
        }
    }

    // ================= phase 0c: load resident stacked B tile (once) =================
    const int n0 = (cta & 15) * 64;                      // dual-phase n tile
    {
        for (int ch = tid; ch < 2 * 64 * 64; ch += NTHR) {
            int half = ch >> 12;
            int rem = ch & 4095;
            int rowB = rem >> 6;
            int c4 = (rem & 63) * 4;
            int colp = n0 + rowB;
            int d = colp >> 2, j = colp & 3;
            const float* src = half ? ((j == 0) ? Wr : Gr) : ((j == 0) ? Wl : Gl);
            int srow = (j == 0) ? d : (j - 1) * 256 + d;
            *(float4*)&pool[half * BR_HALF + rowB * SB + c4] =
                *(const float4*)&src[(size_t)srow * 256 + c4];
        }
    }

    grid_bar();

    // ========== phase 1..7: fused dual GEMM + gate (B resident, A streamed) =========
    {
        const int m0 = (cta >> 4) * 96;
        const int wm = warp >> 1, wn = warp & 1;         // 0..5, 0..1
        const int ar0 = tid >> 3,          ac0 = (tid & 7) * 4;
        const int ar1 = (tid + 384) >> 3,  ac1 = ((tid + 384) & 7) * 4;
        const int ar2 = (tid + 768) >> 3,  ac2 = ((tid + 768) & 7) * 4;   // tid<8

        // sl-invariant shared read bases
        const float* bbase[4][2];
#pragma unroll
        for (int ni = 0; ni < 4; ni++) {
            int rowB = wn * 32 + ni * 8 + g;
            bbase[ni][0] = pool + rowB * SB + 2 * c;
            bbase[ni][1] = pool + BR_HALF + rowB * SB + 2 * c;
        }
        const float* abase[2] = { pool + DA_OFF(0) + (wm * 16 + g) * 40 + 2 * c,
                                  pool + DA_OFF(1) + (wm * 16 + g) * 40 + 2 * c };

        for (int sl = 1; sl <= 7; sl++) {
            const int M = L - sl;
            const float* Aht = g_ht[sl - 1];
            float* htout = g_ht[sl];
            float acc[4][4] = {};

            cpa16(&pool[DA_OFF(0) + ar0 * 40 + ac0], &Aht[(size_t)(m0 + ar0) * 256 + ac0]);
            cpa16(&pool[DA_OFF(0) + ar1 * 40 + ac1], &Aht[(size_t)(m0 + ar1) * 256 + ac1]);
            if (tid < 8)
                cpa16(&pool[DA_OFF(0) + ar2 * 40 + ac2], &Aht[(size_t)(m0 + ar2) * 256 + ac2]);
            CP_COMMIT();

#pragma unroll
            for (int step = 0; step < 8; step++) {
                const int s = step & 1;
                CP_WAIT(0);
                __syncthreads();
                if (step + 1 < 8) {
                    const int k0 = (step + 1) * 32, s2 = s ^ 1;
                    cpa16(&pool[DA_OFF(s2) + ar0 * 40 + ac0],
                          &Aht[(size_t)(m0 + ar0) * 256 + k0 + ac0]);
                    cpa16(&pool[DA_OFF(s2) + ar1 * 40 + ac1],
                          &Aht[(size_t)(m0 + ar1) * 256 + k0 + ac1]);
                    if (tid < 8)
                        cpa16(&pool[DA_OFF(s2) + ar2 * 40 + ac2],
                              &Aht[(size_t)(m0 + ar2) * 256 + k0 + ac2]);
                    CP_COMMIT();
                }
#pragma unroll
                for (int kc = 0; kc < 2 * 2; kc++) {
                    const float* ab = abase[s] + kc * 8;
                    float2 fa0 = *(const float2*)ab;
                    float2 fa1 = *(const float2*)(ab + 320);
                    float2 fr0 = *(const float2*)(ab + 40);
                    float2 fr1 = *(const float2*)(ab + 360);
                    const int kg = step * 32 + kc * 8;
#pragma unroll
                    for (int ni = 0; ni < 4; ni++) {
                        float2 fbl = *(const float2*)(bbase[ni][0] + kg);
                        float2 fbr = *(const float2*)(bbase[ni][1] + kg);
                        mma_tf32(acc[ni][0], acc[ni][1], acc[ni][2], acc[ni][3],
                                 F2U(fa0.x), F2U(fa1.x), F2U(fa0.y), F2U(fa1.y),
                                 F2U(fbl.x), F2U(fbl.y));
                        mma_tf32(acc[ni][0], acc[ni][1], acc[ni][2], acc[ni][3],
                                 F2U(fr0.x), F2U(fr1.x), F2U(fr0.y), F2U(fr1.y),
                                 F2U(fbr.x), F2U(fbr.y));
                    }
                }
            }
            // ---- fused gate epilogue ----
#pragma unroll
            for (int ni = 0; ni < 4; ni++) {
                int colb = n0 + wn * 32 + ni * 8 + 2 * c;
                float b0 = g_biasS[colb], b1 = g_biasS[colb + 1];
                float z00 = acc[ni][0] + b0, z01 = acc[ni][1] + b1;
                float z10 = acc[ni][2] + b0, z11 = acc[ni][3] + b1;
                float w00 = __shfl_xor_sync(0xffffffffu, z00, 1);
                float w01 = __shfl_xor_sync(0xffffffffu, z01, 1);
                float w10 = __shfl_xor_sync(0xffffffffu, z10, 1);
                float w11 = __shfl_xor_sync(0xffffffffu, z11, 1);
                if ((c & 1) == 0) {
                    int d = colb >> 2;
                    int row0 = m0 + wm * 16 + g;
#pragma unroll
                    for (int rr = 0; rr < 2; rr++) {
                        int row = row0 + rr * 8;
                        if (row < M) {
                            float zh  = rr ? z10 : z00;
                            float zg0 = rr ? z11 : z01;
                            float zg1 = rr ? w10 : w00;
                            float zg2 = rr ? w11 : w01;
                            float lft = Aht[(size_t)row * 256 + d];
                            float rgt = Aht[(size_t)(row + 1) * 256 + d];
                            float hh = 4.f / (1.f + __expf(-zh)) - 2.f;
                            float mx = fmaxf(zg0, fmaxf(zg1, zg2));
                            float e0 = __expf(zg0 - mx), e1 = __expf(zg1 - mx),
                                  e2 = __expf(zg2 - mx);
                            float inv = 1.f / (e0 + e1 + e2);
                            htout[(size_t)row * 256 + d] =
                                (e0 * hh + e1 * lft + e2 * rgt) * inv;
                        }
                    }
                }
            }
            grid_bar();
        }
    }

    // ================= phase 8: tag scores + exp gather (B region dead) =============
    {
        for (int i = tid; i < NT * D; i += NTHR) pool[i] = Wt[i];
        __syncthreads();
#pragma unroll
        for (int rep = 0; rep < 4; rep++) {
            int gw = cta * 12 + warp + rep * 1536;       // 0..6143
            int sl = gw / L;
            int pos = gw - sl * L;
            if (pos + sl < L) {
                const float* hp = g_ht[sl] + (size_t)pos * D;
                float4 h0 = *(const float4*)&hp[lane * 8];
                float4 h1 = *(const float4*)&hp[lane * 8 + 4];
                float hv[8] = {h0.x,h0.y,h0.z,h0.w,h1.x,h1.y,h1.z,h1.w};
                int i_end = pos + sl, kk = 7 - sl;
#pragma unroll
                for (int t = 0; t < NT; t++) {
                    const float* wp = &pool[t * D + lane * 8];
                    float4 w0 = *(const float4*)wp;
                    float4 w1 = *(const float4*)(wp + 4);
                    float s = hv[0]*w0.x + hv[1]*w0.y + hv[2]*w0.z + hv[3]*w0.w
                            + hv[4]*w1.x + hv[5]*w1.y + hv[6]*w1.z + hv[7]*w1.w;
#pragma unroll
                    for (int o = 16; o; o >>= 1) s += __shfl_xor_sync(0xffffffffu, s, o);
                    if (lane == 0) {
                        float val = s + bt[t];
                        g_tagsc[sl][pos * NT + t] = val;
                        g_ex[((size_t)i_end * NT + t) * SPAN + kk] = __expf(val);
                    }
                }
            }
        }
    }

    grid_bar();

    // ================= phase 9: chunk transfer matrices (128*9 = 1152 runs) ==========
    if (warp < 9) {
        const int run = cta * 9 + warp;
        const int chunk = run / 96, j = run - chunk * 96;
        const int slotj = j / 12, tj = j - slotj * 12;
        const int t2 = (lane < 12) ? lane : 11;

        float eTc[12];
#pragma unroll
        for (int t1 = 0; t1 < 12; t1++) eTc[t1] = __expf(trans[t1 * 12 + t2]);

        float Cw[8];
#pragma unroll
        for (int k = 0; k < 8; k++) Cw[k] = 0.f;
        if (lane == tj) Cw[slotj] = 1.f;
        float sc = 0.f;
        float lastA = 0.f;

        const float4* exb = (const float4*)(g_ex + ((size_t)(chunk * 64) * 12 + t2) * 8);
        float4 c0 = exb[0], c1 = exb[1];
        float4 n0v = exb[24], n1v = exb[25];

        for (int blk = 0; blk < 8; blk++) {
#pragma unroll
            for (int u = 0; u < 8; u++) {
                const int li = blk * 8 + u;
                float4 f0 = c0, f1 = c1;
                c0 = n0v; c1 = n1v;
                if (li + 2 < 64) {
                    n0v = exb[(li + 2) * 24];
                    n1v = exb[(li + 2) * 24 + 1];
                }
                float e0=f0.x,e1=f0.y,e2=f0.z,e3=f0.w,e4=f1.x,e5=f1.y,e6=f1.z,e7=f1.w;
                float v01 = fmaf(e1, Cw[(u + 1) & 7], e0 * Cw[(u + 0) & 7]);
                float v23 = fmaf(e3, Cw[(u + 3) & 7], e2 * Cw[(u + 2) & 7]);
                float v45 = fmaf(e5, Cw[(u + 5) & 7], e4 * Cw[(u + 4) & 7]);
                float v6  = e6 * Cw[(u + 6) & 7];
                float A = fmaf(e7, Cw[(u + 7) & 7], (v01 + v23) + (v45 + v6));
                lastA = A;
                float bnA = 0.f, bnB = 0.f;
#pragma unroll
                for (int t1 = 0; t1 < 6; t1++) {
                    bnA = fmaf(eTc[t1],     __shfl_sync(0xffffffffu, A, t1),     bnA);
                    bnB = fmaf(eTc[t1 + 6], __shfl_sync(0xffffffffu, A, t1 + 6), bnB);
                }
                Cw[u] = bnA + bnB;
            }
            if (blk != 7) {
                float m = (lane < 12) ? Cw[7] : 0.f;
#pragma unroll
                for (int o = 16; o; o >>= 1) m = fmaxf(m, __shfl_xor_sync(0xffffffffu, m, o));
                if (m < 1e-30f) m = 1.f;
                float inv = 1.f / m;
#pragma unroll
                for (int k = 0; k < 8; k++) Cw[k] *= inv;
                sc += __logf(m);
            }
        }

        if (chunk < 11) {
            if (lane < 12) {
#pragma unroll
                for (int slot = 0; slot < 8; slot++)
                    g_GT[((size_t)chunk * 96 + j) * 96 + slot * 12 + lane] = Cw[slot];
            }
            if (lane == 0) g_sc[chunk * 96 + j] = sc;
        } else {
            if (lane < 12) g_R[j * 12 + lane] = lastA;
            if (lane == 0) g_sc[11 * 96 + j] = sc;
        }
    }

    grid_bar();
    if (cta != 0) return;

    // ================= phase 10 (CTA 0 only): gold + chunk matvec chain ==============
    {
        float* s_sh   = pool;            // 96
        float* st_sh  = pool + 96;       // 96
        float* lv     = pool + 192;      // 11
        float* wred   = pool + 204;      // 3
        float* wred2  = pool + 208;      // 3
        float* gold_sh= pool + 212;      // 1
        float* scall  = pool + 256;      // 1152
        float* Rsh    = pool + 1472;     // 1152
        float* part   = pool + 2688;     // 768

        __syncthreads();
        for (int i = tid; i < 1152; i += NTHR) { scall[i] = g_sc[i]; Rsh[i] = g_R[i]; }

        if (warp == 0) {
            float gold = 0.f;
            for (int s = lane; s < 96; s += 32) {
                int i  = tags[s * 4 + 0];
                int j  = tags[s * 4 + 1];
                int pr = tags[s * 4 + 2];
                int t  = tags[s * 4 + 3];
                int sl = j - i;
                float base = (sl >= 0 && sl < SPAN && i >= 0 && i + sl < L)
                           ? g_tagsc[sl][i * NT + t] : bt[t];
                gold += base + trans[pr * NT + t];
            }
#pragma unroll
            for (int o = 16; o; o >>= 1) gold += __shfl_xor_sync(0xffffffffu, gold, o);
            if (lane == 0) gold_sh[0] = gold;
        }
        if (tid < 96) s_sh[tid] = (tid >= 84) ? expf(trans[10 * 12 + (tid - 84)]) : 0.f;
        __syncthreads();

        float Sacc = 0.f, mc = 0.f;
        for (int cch = 0; cch < 12; cch++) {
            float m = (tid < 96) ? scall[cch * 96 + tid] : -3e38f;
#pragma unroll
            for (int off = 16; off; off >>= 1) m = fmaxf(m, __shfl_xor_sync(0xffffffffu, m, off));
            if (tid < 96 && lane == 0) wred[warp] = m;
            __syncthreads();
            mc = fmaxf(fmaxf(wred[0], wred[1]), wred[2]);
            if (tid < 96) st_sh[tid] = s_sh[tid] * expf(scall[cch * 96 + tid] - mc);
            __syncthreads();

            if (cch < 11) {
                if (warp < 8) {
                    const float* G = g_GT + (size_t)cch * 9216 + (size_t)(warp * 12) * 96;
                    const float* sv = &st_sh[warp * 12];
                    float a0 = 0.f, a1 = 0.f, a2 = 0.f;
#pragma unroll
                    for (int j = 0; j < 12; j++) {
                        float svj = sv[j];
                        a0 = fmaf(G[j * 96 + lane],      svj, a0);
                        a1 = fmaf(G[j * 96 + lane + 32], svj, a1);
                        a2 = fmaf(G[j * 96 + lane + 64], svj, a2);
                    }
                    part[warp * 96 + lane]      = a0;
                    part[warp * 96 + lane + 32] = a1;
                    part[warp * 96 + lane + 64] = a2;
                }
                __syncthreads();
                float snew = 0.f;
                if (tid < 96) {
                    snew = ((part[tid] + part[96 + tid]) + (part[192 + tid] + part[288 + tid]))
                         + ((part[384 + tid] + part[480 + tid]) + (part[576 + tid] + part[672 + tid]));
                }
                float m2 = (tid < 96) ? snew : 0.f;
#pragma unroll
                for (int off = 16; off; off >>= 1) m2 = fmaxf(m2, __shfl_xor_sync(0xffffffffu, m2, off));
                if (tid < 96 && lane == 0) wred2[warp] = m2;
                __syncthreads();
                float mx = fmaxf(fmaxf(wred2[0], wred2[1]), wred2[2]);
                if (mx < 1e-30f) mx = 1.f;
                if (tid < 96) s_sh[tid] = snew / mx;
                Sacc += mc + logf(mx);
                __syncthreads();
            }
        }

        if (tid < 11) {
            float a0 = 0.f, a1 = 0.f, a2 = 0.f, a3 = 0.f;
#pragma unroll 4
            for (int j = 0; j < 96; j += 4) {
                a0 = fmaf(Rsh[(j + 0) * 12 + tid], st_sh[j + 0], a0);
                a1 = fmaf(Rsh[(j + 1) * 12 + tid], st_sh[j + 1], a1);
                a2 = fmaf(Rsh[(j + 2) * 12 + tid], st_sh[j + 2], a2);
                a3 = fmaf(Rsh[(j + 3) * 12 + tid], st_sh[j + 3], a3);
            }
            lv[tid] = logf((a0 + a1) + (a2 + a3));
        }
        __syncthreads();
        if (tid == 0) {
            float logZ = 11.f * (Sacc + mc);
            for (int t = 0; t < 11; t++) logZ += lv[t];
            out[0] = logZ - gold_sh[0];
        }
    }
}

// ---------------- launch ----------------
extern "C" void kernel_launch(void* const* d_in, const int* in_sizes, int n_in,
                              void* d_out, int out_size)
{
    const float* feats = (const float*)d_in[0];
    const int*   tags  = (const int*)d_in[1];
    const float* Wd    = (const float*)d_in[2];
    const float* bd    = (const float*)d_in[3];
    const float* Wl    = (const float*)d_in[4];
    const float* bl    = (const float*)d_in[5];
    const float* Wr    = (const float*)d_in[6];
    const float* br    = (const float*)d_in[7];
    const float* Gl    = (const float*)d_in[8];
    const float* bgl   = (const float*)d_in[9];
    const float* Gr    = (const float*)d_in[10];
    const float* bgr   = (const float*)d_in[11];
    const float* Wt    = (const float*)d_in[12];
    const float* bt    = (const float*)d_in[13];
    const float* trans = (const float*)d_in[14];
    float* out = (float*)d_out;

    cudaFuncSetAttribute(mega_kernel, cudaFuncAttributeMaxDynamicSharedMemorySize,
                         SMEM_BYTES);
    mega_kernel<<<NCTA, NTHR, SMEM_BYTES>>>(feats, Wd, bd, Wl, Wr, Gl, Gr,
                                            bl, br, bgl, bgr, Wt, bt, trans, tags, out);
}

// round 12
// speedup vs baseline: 1.1768x; 1.0497x over previous
#include <cuda_runtime.h>
#include <cstdint>

#define L    768
#define D    256
#define NT   12
#define SPAN 8
#define NCTA 128
#define NTHR 384

// ---------------- device scratch (static, no allocs) ----------------
__device__ __align__(16) float g_ht[8][L * D];        // ht per span-length diagonal
__device__ __align__(16) float g_biasS[1024];         // stacked bias
__device__ __align__(16) float g_tagsc[8][L * NT];    // tag scores per diagonal (for gold)
__device__ __align__(16) float g_ex[L * NT * SPAN];   // exp(span scores) [i][t2][k]
__device__ __align__(16) float g_GT[11 * 96 * 96];    // chunk transfer matrices [c][j][o]
__device__ __align__(16) float g_sc[12 * 96];         // per-column log scales
__device__ __align__(16) float g_R[96 * 12];          // last chunk: A_767 rows [j][t2]
__device__ unsigned g_cnt;                            // grid barrier state (zero-init)
__device__ unsigned g_gen;

#define F2U(x) __float_as_uint(x)

__device__ __forceinline__ void mma_tf32(float& c0, float& c1, float& c2, float& c3,
                                         uint32_t a0, uint32_t a1, uint32_t a2, uint32_t a3,
                                         uint32_t b0, uint32_t b1)
{
    asm volatile("mma.sync.aligned.m16n8k8.row.col.f32.tf32.tf32.f32 "
                 "{%0,%1,%2,%3}, {%4,%5,%6,%7}, {%8,%9}, {%0,%1,%2,%3};\n"
                 : "+f"(c0), "+f"(c1), "+f"(c2), "+f"(c3)
                 : "r"(a0), "r"(a1), "r"(a2), "r"(a3), "r"(b0), "r"(b1));
}

__device__ __forceinline__ void cpa16(float* dst, const float* src)
{
    uint32_t d = (uint32_t)__cvta_generic_to_shared(dst);
    asm volatile("cp.async.cg.shared.global [%0], [%1], 16;\n" :: "r"(d), "l"(src));
}
#define CP_COMMIT() asm volatile("cp.async.commit_group;\n")
#define CP_WAIT(n)  asm volatile("cp.async.wait_group %0;\n" :: "n"(n))

// ---------------- software grid barrier (128 CTAs, 1/SM guaranteed) ----------------
__device__ __forceinline__ void grid_bar()
{
    __syncthreads();
    if (threadIdx.x == 0) {
        __threadfence();
        unsigned gen = *(volatile unsigned*)&g_gen;
        if (atomicAdd(&g_cnt, 1u) == NCTA - 1u) {
            g_cnt = 0u;
            __threadfence();
            atomicAdd(&g_gen, 1u);
        } else {
            while (*(volatile unsigned*)&g_gen == gen) __nanosleep(32);
        }
        __threadfence();
    }
    __syncthreads();
}

// ---------------- dynamic shared pool layout (floats) ----------------
// B resident : BR[half][64 rows][stride 264]  at 0        (2*64*264 = 33792)
// dual A     : DA(s) = 33792 + s*3880         (97 rows x stride 40, 2 stages)
// ribbons    : RIB_IN = 41552 (97x20), RIB_OUT = 43492 (96x20)
// h aliases  : HA(s) = 33792 + s*1920 ; HB(s) = 33792+3840 + s*1280
#define BR_HALF     16896
#define SB          264
#define DA_OFF(s)   (33792 + (s) * 3880)
#define RIB_IN      41552
#define RIB_OUT     43492
#define HA_OFF(s)   (33792 + (s) * 1920)
#define HB_OFF(s)   (33792 + 3840 + (s) * 1280)
#define POOL_FLOATS 45412
#define SMEM_BYTES  (POOL_FLOATS * 4)

// ================== persistent mega kernel ==================
__global__ void __launch_bounds__(NTHR, 1) mega_kernel(
    const float* __restrict__ feats, const float* __restrict__ Wd,
    const float* __restrict__ bd,
    const float* __restrict__ Wl, const float* __restrict__ Wr,
    const float* __restrict__ Gl, const float* __restrict__ Gr,
    const float* __restrict__ bl, const float* __restrict__ br,
    const float* __restrict__ bgl, const float* __restrict__ bgr,
    const float* __restrict__ Wt, const float* __restrict__ bt,
    const float* __restrict__ trans, const int* __restrict__ tags,
    float* __restrict__ out)
{
    extern __shared__ __align__(16) float pool[];
    const int cta = blockIdx.x;
    const int tid = threadIdx.x;
    const int lane = tid & 31, warp = tid >> 5;
    const int g = lane >> 2, c = lane & 3;

    // ================= phase 0a: zero g_ex, build g_biasS =================
    for (int i = cta * NTHR + tid; i < L * NT * SPAN; i += NCTA * NTHR) g_ex[i] = 0.f;
    if (cta == 0) {
        for (int i = tid; i < 1024; i += NTHR) {
            int dd = i >> 2, jj = i & 3;
            g_biasS[i] = (jj == 0) ? (bl[dd] + br[dd])
                                   : (bgl[(jj - 1) * 256 + dd] + bgr[(jj - 1) * 256 + dd]);
        }
    }

    // ================= phase 0b: h = feats @ Wd^T + bd  (BM=48, BN=32, all CTAs) ===
    {
        const int m0h = (cta >> 3) * 48, n0h = (cta & 7) * 32;
        const int wmh = warp >> 2, wnh = warp & 3;       // 0..2, 0..3
        const int har = tid >> 3, hac = (tid & 7) * 4;   // 384 A f4 chunks
        const bool do_b = tid < 256;
        float acch[4] = {};

        cpa16(&pool[HA_OFF(0) + har * 40 + hac], &feats[(size_t)(m0h + har) * 512 + hac]);
        if (do_b) cpa16(&pool[HB_OFF(0) + har * 40 + hac], &Wd[(size_t)(n0h + har) * 512 + hac]);
        CP_COMMIT();

#pragma unroll
        for (int step = 0; step < 16; step++) {
            const int s = step & 1;
            CP_WAIT(0);
            __syncthreads();
            if (step + 1 < 16) {
                const int k0 = (step + 1) * 32, s2 = s ^ 1;
                cpa16(&pool[HA_OFF(s2) + har * 40 + hac],
                      &feats[(size_t)(m0h + har) * 512 + k0 + hac]);
                if (do_b) cpa16(&pool[HB_OFF(s2) + har * 40 + hac],
                                &Wd[(size_t)(n0h + har) * 512 + k0 + hac]);
                CP_COMMIT();
            }
#pragma unroll
            for (int kc = 0; kc < 4; kc++) {
                const int ko = kc * 8 + 2 * c;
                const float* p = &pool[HA_OFF(s) + (wmh * 16 + g) * 40 + ko];
                float2 fa0 = *(const float2*)p;
                float2 fa1 = *(const float2*)(p + 8 * 40);
                const float* pb = &pool[HB_OFF(s) + (wnh * 8 + g) * 40 + ko];
                float2 fb = *(const float2*)pb;
                mma_tf32(acch[0], acch[1], acch[2], acch[3],
                         F2U(fa0.x), F2U(fa1.x), F2U(fa0.y), F2U(fa1.y),
                         F2U(fb.x), F2U(fb.y));
            }
        }
        {
            int col = n0h + wnh * 8 + 2 * c;
            int row0 = m0h + wmh * 16 + g;
            g_ht[0][(size_t)row0 * 256 + col]           = acch[0] + bd[col];
            g_ht[0][(size_t)row0 * 256 + col + 1]       = acch[1] + bd[col + 1];
            g_ht[0][(size_t)(row0 + 8) * 256 + col]     = acch[2] + bd[col];
            g_ht[0][(size_t)(row0 + 8) * 256 + col + 1] = acch[3] + bd[col + 1];
        }
    }

    // ================= phase 0c: load resident stacked B tile (once) =================
    const int n0 = (cta & 15) * 64;                      // dual-phase n tile
    {
        for (int ch = tid; ch < 2 * 64 * 64; ch += NTHR) {
            int half = ch >> 12;
            int rem = ch & 4095;
            int rowB = rem >> 6;
            int c4 = (rem & 63) * 4;
            int colp = n0 + rowB;
            int d = colp >> 2, j = colp & 3;
            const float* src = half ? ((j == 0) ? Wr : Gr) : ((j == 0) ? Wl : Gl);
            int srow = (j == 0) ? d : (j - 1) * 256 + d;
            *(float4*)&pool[half * BR_HALF + rowB * SB + c4] =
                *(const float4*)&src[(size_t)srow * 256 + c4];
        }
    }

    grid_bar();

    // ========== phase 1..7: fused dual GEMM + gate (B resident, A streamed) =========
    {
        const int m0 = (cta >> 4) * 96;
        const int wm = warp >> 1, wn = warp & 1;         // 0..5, 0..1
        const int ar0 = tid >> 3,          ac0 = (tid & 7) * 4;
        const int ar1 = (tid + 384) >> 3,  ac1 = ((tid + 384) & 7) * 4;
        const int ar2 = (tid + 768) >> 3,  ac2 = ((tid + 768) & 7) * 4;   // tid<8
        const int q = cta & 15;                          // d0 = q*16
        const int qd = q >> 1;                           // capture step
        const int qoff = (q & 1) * 16;                   // col offset within stage

        // sl-invariant shared read bases
        const float* bbase[4][2];
#pragma unroll
        for (int ni = 0; ni < 4; ni++) {
            int rowB = wn * 32 + ni * 8 + g;
            bbase[ni][0] = pool + rowB * SB + 2 * c;
            bbase[ni][1] = pool + BR_HALF + rowB * SB + 2 * c;
        }
        const float* abase[2] = { pool + DA_OFF(0) + (wm * 16 + g) * 40 + 2 * c,
                                  pool + DA_OFF(1) + (wm * 16 + g) * 40 + 2 * c };
        // sl-invariant bias (g_biasS written by cta0 before grid_bar)
        float bpre[4][2];
#pragma unroll
        for (int ni = 0; ni < 4; ni++) {
            int colb = n0 + wn * 32 + ni * 8 + 2 * c;
            bpre[ni][0] = g_biasS[colb];
            bpre[ni][1] = g_biasS[colb + 1];
        }

        for (int sl = 1; sl <= 7; sl++) {
            const int M = L - sl;
            const float* Aht = g_ht[sl - 1];
            float* htout = g_ht[sl];
            float acc[4][4] = {};

            cpa16(&pool[DA_OFF(0) + ar0 * 40 + ac0], &Aht[(size_t)(m0 + ar0) * 256 + ac0]);
            cpa16(&pool[DA_OFF(0) + ar1 * 40 + ac1], &Aht[(size_t)(m0 + ar1) * 256 + ac1]);
            if (tid < 8)
                cpa16(&pool[DA_OFF(0) + ar2 * 40 + ac2], &Aht[(size_t)(m0 + ar2) * 256 + ac2]);
            CP_COMMIT();

#pragma unroll
            for (int step = 0; step < 8; step++) {
                const int s = step & 1;
                CP_WAIT(0);
                __syncthreads();
                if (step + 1 < 8) {
                    const int k0 = (step + 1) * 32, s2 = s ^ 1;
                    cpa16(&pool[DA_OFF(s2) + ar0 * 40 + ac0],
                          &Aht[(size_t)(m0 + ar0) * 256 + k0 + ac0]);
                    cpa16(&pool[DA_OFF(s2) + ar1 * 40 + ac1],
                          &Aht[(size_t)(m0 + ar1) * 256 + k0 + ac1]);
                    if (tid < 8)
                        cpa16(&pool[DA_OFF(s2) + ar2 * 40 + ac2],
                              &Aht[(size_t)(m0 + ar2) * 256 + k0 + ac2]);
                    CP_COMMIT();
                }
                // ---- ribbon capture: A columns [d0, d0+16) live in this stage ----
                if (step == qd) {
                    int rowl = tid >> 2, c4 = (tid & 3) * 4;
                    float4 v = *(const float4*)&pool[DA_OFF(s) + rowl * 40 + qoff + c4];
                    *(float4*)&pool[RIB_IN + rowl * 20 + c4] = v;
                    if (tid < 4) {
                        float4 w = *(const float4*)&pool[DA_OFF(s) + 96 * 40 + qoff + tid * 4];
                        *(float4*)&pool[RIB_IN + 96 * 20 + tid * 4] = w;
                    }
                }
#pragma unroll
                for (int kc = 0; kc < 4; kc++) {
                    const float* ab = abase[s] + kc * 8;
                    float2 fa0 = *(const float2*)ab;
                    float2 fa1 = *(const float2*)(ab + 320);
                    float2 fr0 = *(const float2*)(ab + 40);
                    float2 fr1 = *(const float2*)(ab + 360);
                    const int kg = step * 32 + kc * 8;
#pragma unroll
                    for (int ni = 0; ni < 4; ni++) {
                        float2 fbl = *(const float2*)(bbase[ni][0] + kg);
                        float2 fbr = *(const float2*)(bbase[ni][1] + kg);
                        mma_tf32(acc[ni][0], acc[ni][1], acc[ni][2], acc[ni][3],
                                 F2U(fa0.x), F2U(fa1.x), F2U(fa0.y), F2U(fa1.y),
                                 F2U(fbl.x), F2U(fbl.y));
                        mma_tf32(acc[ni][0], acc[ni][1], acc[ni][2], acc[ni][3],
                                 F2U(fr0.x), F2U(fr1.x), F2U(fr0.y), F2U(fr1.y),
                                 F2U(fbr.x), F2U(fbr.y));
                    }
                }
            }
            __syncthreads();           // rib_in complete (covers qd==7 case)

            // ---- fused gate epilogue: smem in, smem out ----
#pragma unroll
            for (int ni = 0; ni < 4; ni++) {
                float z00 = acc[ni][0] + bpre[ni][0], z01 = acc[ni][1] + bpre[ni][1];
                float z10 = acc[ni][2] + bpre[ni][0], z11 = acc[ni][3] + bpre[ni][1];
                float w00 = __shfl_xor_sync(0xffffffffu, z00, 1);
                float w01 = __shfl_xor_sync(0xffffffffu, z01, 1);
                float w10 = __shfl_xor_sync(0xffffffffu, z10, 1);
                float w11 = __shfl_xor_sync(0xffffffffu, z11, 1);
                if ((c & 1) == 0) {
                    int dl = wn * 8 + ni * 2 + (c >> 1);
                    int rowl0 = wm * 16 + g;
#pragma unroll
                    for (int rr = 0; rr < 2; rr++) {
                        int rowl = rowl0 + rr * 8;
                        float zh  = rr ? z10 : z00;
                        float zg0 = rr ? z11 : z01;
                        float zg1 = rr ? w10 : w00;
                        float zg2 = rr ? w11 : w01;
                        float lft = pool[RIB_IN + rowl * 20 + dl];
                        float rgt = pool[RIB_IN + (rowl + 1) * 20 + dl];
                        float hh = 4.f / (1.f + __expf(-zh)) - 2.f;
                        float mx = fmaxf(zg0, fmaxf(zg1, zg2));
                        float e0 = __expf(zg0 - mx), e1 = __expf(zg1 - mx),
                              e2 = __expf(zg2 - mx);
                        float inv = 1.f / (e0 + e1 + e2);
                        pool[RIB_OUT + rowl * 20 + dl] =
                            (e0 * hh + e1 * lft + e2 * rgt) * inv;
                    }
                }
            }
            __syncthreads();
            // ---- coalesced store of the 96x16 output ribbon ----
            {
                int rowl = tid >> 2, c4 = (tid & 3) * 4;
                if (m0 + rowl < M) {
                    float4 v = *(const float4*)&pool[RIB_OUT + rowl * 20 + c4];
                    *(float4*)&htout[(size_t)(m0 + rowl) * 256 + q * 16 + c4] = v;
                }
            }
            grid_bar();
        }
    }

    // ================= phase 8: tag scores + exp gather (B region dead) =============
    {
        for (int i = tid; i < NT * D; i += NTHR) pool[i] = Wt[i];
        __syncthreads();
#pragma unroll
        for (int rep = 0; rep < 4; rep++) {
            int gw = cta * 12 + warp + rep * 1536;       // 0..6143
            int sl = gw / L;
            int pos = gw - sl * L;
            if (pos + sl < L) {
                const float* hp = g_ht[sl] + (size_t)pos * D;
                float4 h0 = *(const float4*)&hp[lane * 8];
                float4 h1 = *(const float4*)&hp[lane * 8 + 4];
                float hv[8] = {h0.x,h0.y,h0.z,h0.w,h1.x,h1.y,h1.z,h1.w};
                int i_end = pos + sl, kk = 7 - sl;
#pragma unroll
                for (int t = 0; t < NT; t++) {
                    const float* wp = &pool[t * D + lane * 8];
                    float4 w0 = *(const float4*)wp;
                    float4 w1 = *(const float4*)(wp + 4);
                    float s = hv[0]*w0.x + hv[1]*w0.y + hv[2]*w0.z + hv[3]*w0.w
                            + hv[4]*w1.x + hv[5]*w1.y + hv[6]*w1.z + hv[7]*w1.w;
#pragma unroll
                    for (int o = 16; o; o >>= 1) s += __shfl_xor_sync(0xffffffffu, s, o);
                    if (lane == 0) {
                        float val = s + bt[t];
                        g_tagsc[sl][pos * NT + t] = val;
                        g_ex[((size_t)i_end * NT + t) * SPAN + kk] = __expf(val);
                    }
                }
            }
        }
    }

    grid_bar();

    // ================= phase 9: chunk transfer matrices (128*9 = 1152 runs) ==========
    if (warp < 9) {
        const int run = cta * 9 + warp;
        const int chunk = run / 96, j = run - chunk * 96;
        const int slotj = j / 12, tj = j - slotj * 12;
        const int t2 = (lane < 12) ? lane : 11;

        float eTc[12];
#pragma unroll
        for (int t1 = 0; t1 < 12; t1++) eTc[t1] = __expf(trans[t1 * 12 + t2]);

        float Cw[8];
#pragma unroll
        for (int k = 0; k < 8; k++) Cw[k] = 0.f;
        if (lane == tj) Cw[slotj] = 1.f;
        float sc = 0.f;
        float lastA = 0.f;

        const float4* exb = (const float4*)(g_ex + ((size_t)(chunk * 64) * 12 + t2) * 8);
        float4 c0 = exb[0], c1 = exb[1];
        float4 n0v = exb[24], n1v = exb[25];

        for (int blk = 0; blk < 8; blk++) {
#pragma unroll
            for (int u = 0; u < 8; u++) {
                const int li = blk * 8 + u;
                float4 f0 = c0, f1 = c1;
                c0 = n0v; c1 = n1v;
                if (li + 2 < 64) {
                    n0v = exb[(li + 2) * 24];
                    n1v = exb[(li + 2) * 24 + 1];
                }
                float e0=f0.x,e1=f0.y,e2=f0.z,e3=f0.w,e4=f1.x,e5=f1.y,e6=f1.z,e7=f1.w;
                float v01 = fmaf(e1, Cw[(u + 1) & 7], e0 * Cw[(u + 0) & 7]);
                float v23 = fmaf(e3, Cw[(u + 3) & 7], e2 * Cw[(u + 2) & 7]);
                float v45 = fmaf(e5, Cw[(u + 5) & 7], e4 * Cw[(u + 4) & 7]);
                float v6  = e6 * Cw[(u + 6) & 7];
                float A = fmaf(e7, Cw[(u + 7) & 7], (v01 + v23) + (v45 + v6));
                lastA = A;
                float bnA = 0.f, bnB = 0.f;
#pragma unroll
                for (int t1 = 0; t1 < 6; t1++) {
                    bnA = fmaf(eTc[t1],     __shfl_sync(0xffffffffu, A, t1),     bnA);
                    bnB = fmaf(eTc[t1 + 6], __shfl_sync(0xffffffffu, A, t1 + 6), bnB);
                }
                Cw[u] = bnA + bnB;
            }
            if (blk != 7) {
                float m = (lane < 12) ? Cw[7] : 0.f;
#pragma unroll
                for (int o = 16; o; o >>= 1) m = fmaxf(m, __shfl_xor_sync(0xffffffffu, m, o));
                if (m < 1e-30f) m = 1.f;
                float inv = 1.f / m;
#pragma unroll
                for (int k = 0; k < 8; k++) Cw[k] *= inv;
                sc += __logf(m);
            }
        }

        if (chunk < 11) {
            if (lane < 12) {
#pragma unroll
                for (int slot = 0; slot < 8; slot++)
                    g_GT[((size_t)chunk * 96 + j) * 96 + slot * 12 + lane] = Cw[slot];
            }
            if (lane == 0) g_sc[chunk * 96 + j] = sc;
        } else {
            if (lane < 12) g_R[j * 12 + lane] = lastA;
            if (lane == 0) g_sc[11 * 96 + j] = sc;
        }
    }

    grid_bar();
    if (cta != 0) return;

    // ================= phase 10 (CTA 0 only): gold + chunk matvec chain ==============
    {
        float* s_sh   = pool;            // 96
        float* st_sh  = pool + 96;       // 96
        float* lv     = pool + 192;      // 11
        float* wred   = pool + 204;      // 3
        float* wred2  = pool + 208;      // 3
        float* gold_sh= pool + 212;      // 1
        float* scall  = pool + 256;      // 1152
        float* Rsh    = pool + 1472;     // 1152
        float* part   = pool + 2688;     // 768

        __syncthreads();
        for (int i = tid; i < 1152; i += NTHR) { scall[i] = g_sc[i]; Rsh[i] = g_R[i]; }

        if (warp == 0) {
            float gold = 0.f;
            for (int s = lane; s < 96; s += 32) {
                int i  = tags[s * 4 + 0];
                int j  = tags[s * 4 + 1];
                int pr = tags[s * 4 + 2];
                int t  = tags[s * 4 + 3];
                int sl = j - i;
                float base = (sl >= 0 && sl < SPAN && i >= 0 && i + sl < L)
                           ? g_tagsc[sl][i * NT + t] : bt[t];
                gold += base + trans[pr * NT + t];
            }
#pragma unroll
            for (int o = 16; o; o >>= 1) gold += __shfl_xor_sync(0xffffffffu, gold, o);
            if (lane == 0) gold_sh[0] = gold;
        }
        if (tid < 96) s_sh[tid] = (tid >= 84) ? expf(trans[10 * 12 + (tid - 84)]) : 0.f;
        __syncthreads();

        float Sacc = 0.f, mc = 0.f;
        for (int cch = 0; cch < 12; cch++) {
            float m = (tid < 96) ? scall[cch * 96 + tid] : -3e38f;
#pragma unroll
            for (int off = 16; off; off >>= 1) m = fmaxf(m, __shfl_xor_sync(0xffffffffu, m, off));
            if (tid < 96 && lane == 0) wred[warp] = m;
            __syncthreads();
            mc = fmaxf(fmaxf(wred[0], wred[1]), wred[2]);
            if (tid < 96) st_sh[tid] = s_sh[tid] * expf(scall[cch * 96 + tid] - mc);
            __syncthreads();

            if (cch < 11) {
                if (warp < 8) {
                    const float* G = g_GT + (size_t)cch * 9216 + (size_t)(warp * 12) * 96;
                    const float* sv = &st_sh[warp * 12];
                    float a0 = 0.f, a1 = 0.f, a2 = 0.f;
#pragma unroll
                    for (int j = 0; j < 12; j++) {
                        float svj = sv[j];
                        a0 = fmaf(G[j * 96 + lane],      svj, a0);
                        a1 = fmaf(G[j * 96 + lane + 32], svj, a1);
                        a2 = fmaf(G[j * 96 + lane + 64], svj, a2);
                    }
                    part[warp * 96 + lane]      = a0;
                    part[warp * 96 + lane + 32] = a1;
                    part[warp * 96 + lane + 64] = a2;
                }
                __syncthreads();
                float snew = 0.f;
                if (tid < 96) {
                    snew = ((part[tid] + part[96 + tid]) + (part[192 + tid] + part[288 + tid]))
                         + ((part[384 + tid] + part[480 + tid]) + (part[576 + tid] + part[672 + tid]));
                }
                float m2 = (tid < 96) ? snew : 0.f;
#pragma unroll
                for (int off = 16; off; off >>= 1) m2 = fmaxf(m2, __shfl_xor_sync(0xffffffffu, m2, off));
                if (tid < 96 && lane == 0) wred2[warp] = m2;
                __syncthreads();
                float mx = fmaxf(fmaxf(wred2[0], wred2[1]), wred2[2]);
                if (mx < 1e-30f) mx = 1.f;
                if (tid < 96) s_sh[tid] = snew / mx;
                Sacc += mc + logf(mx);
                __syncthreads();
            }
        }

        if (tid < 11) {
            float a0 = 0.f, a1 = 0.f, a2 = 0.f, a3 = 0.f;
#pragma unroll 4
            for (int j = 0; j < 96; j += 4) {
                a0 = fmaf(Rsh[(j + 0) * 12 + tid], st_sh[j + 0], a0);
                a1 = fmaf(Rsh[(j + 1) * 12 + tid], st_sh[j + 1], a1);
                a2 = fmaf(Rsh[(j + 2) * 12 + tid], st_sh[j + 2], a2);
                a3 = fmaf(Rsh[(j + 3) * 12 + tid], st_sh[j + 3], a3);
            }
            lv[tid] = logf((a0 + a1) + (a2 + a3));
        }
        __syncthreads();
        if (tid == 0) {
            float logZ = 11.f * (Sacc + mc);
            for (int t = 0; t < 11; t++) logZ += lv[t];
            out[0] = logZ - gold_sh[0];
        }
    }
}

// ---------------- launch ----------------
extern "C" void kernel_launch(void* const* d_in, const int* in_sizes, int n_in,
                              void* d_out, int out_size)
{
    const float* feats = (const float*)d_in[0];
    const int*   tags  = (const int*)d_in[1];
    const float* Wd    = (const float*)d_in[2];
    const float* bd    = (const float*)d_in[3];
    const float* Wl    = (const float*)d_in[4];
    const float* bl    = (const float*)d_in[5];
    const float* Wr    = (const float*)d_in[6];
    const float* br    = (const float*)d_in[7];
    const float* Gl    = (const float*)d_in[8];
    const float* bgl   = (const float*)d_in[9];
    const float* Gr    = (const float*)d_in[10];
    const float* bgr   = (const float*)d_in[11];
    const float* Wt    = (const float*)d_in[12];
    const float* bt    = (const float*)d_in[13];
    const float* trans = (const float*)d_in[14];
    float* out = (float*)d_out;

    cudaFuncSetAttribute(mega_kernel, cudaFuncAttributeMaxDynamicSharedMemorySize,
                         SMEM_BYTES);
    mega_kernel<<<NCTA, NTHR, SMEM_BYTES>>>(feats, Wd, bd, Wl, Wr, Gl, Gr,
                                            bl, br, bgl, bgr, Wt, bt, trans, tags, out);
}

// round 13
// speedup vs baseline: 1.1829x; 1.0052x over previous
#include <cuda_runtime.h>
#include <cstdint>

#define L    768
#define D    256
#define NT   12
#define SPAN 8
#define NCTA 128
#define NTHR 384

// ---------------- device scratch (static, no allocs) ----------------
__device__ __align__(16) float g_ht[8][L * D];        // ht per span-length diagonal
__device__ __align__(16) float g_biasS[1024];         // stacked bias
__device__ __align__(16) float g_tagsc[8][L * NT];    // tag scores per diagonal (for gold)
__device__ __align__(16) float g_ex[L * NT * SPAN];   // exp(span scores) [i][t2][k]
__device__ __align__(16) float g_GT[11 * 96 * 96];    // chunk transfer matrices [c][j][o]
__device__ __align__(16) float g_sc[12 * 96];         // per-column log scales
__device__ __align__(16) float g_R[96 * 12];          // last chunk: A_767 rows [j][t2]
__device__ unsigned g_cnt;                            // grid barrier state (zero-init)
__device__ unsigned g_gen;

#define F2U(x) __float_as_uint(x)

__device__ __forceinline__ void mma_tf32(float& c0, float& c1, float& c2, float& c3,
                                         uint32_t a0, uint32_t a1, uint32_t a2, uint32_t a3,
                                         uint32_t b0, uint32_t b1)
{
    asm volatile("mma.sync.aligned.m16n8k8.row.col.f32.tf32.tf32.f32 "
                 "{%0,%1,%2,%3}, {%4,%5,%6,%7}, {%8,%9}, {%0,%1,%2,%3};\n"
                 : "+f"(c0), "+f"(c1), "+f"(c2), "+f"(c3)
                 : "r"(a0), "r"(a1), "r"(a2), "r"(a3), "r"(b0), "r"(b1));
}

__device__ __forceinline__ void cpa16(float* dst, const float* src)
{
    uint32_t d = (uint32_t)__cvta_generic_to_shared(dst);
    asm volatile("cp.async.cg.shared.global [%0], [%1], 16;\n" :: "r"(d), "l"(src));
}
#define CP_COMMIT() asm volatile("cp.async.commit_group;\n")
#define CP_WAIT(n)  asm volatile("cp.async.wait_group %0;\n" :: "n"(n))

// ---------------- software grid barrier (128 CTAs, 1/SM guaranteed) ----------------
__device__ __forceinline__ void grid_bar()
{
    __syncthreads();
    if (threadIdx.x == 0) {
        __threadfence();
        unsigned gen = *(volatile unsigned*)&g_gen;
        if (atomicAdd(&g_cnt, 1u) == NCTA - 1u) {
            g_cnt = 0u;
            __threadfence();
            atomicAdd(&g_gen, 1u);
        } else {
            while (*(volatile unsigned*)&g_gen == gen) __nanosleep(32);
        }
        __threadfence();
    }
    __syncthreads();
}

// ---------------- dynamic shared pool layout (floats) ----------------
// B resident : BR[half][64 rows][stride 264]  at 0        (2*64*264 = 33792)
// dual A     : DA(s) = 33792 + s*3880         (97 rows x stride 40, 2 stages)
// ribbons    : RIB_IN = 41552 (97x20), RIB_OUT = 43492 (96x20)
// h aliases  : HA(s) = 33792 + s*1920 ; HB(s) = 33792+3840 + s*1280
#define BR_HALF     16896
#define SB          264
#define DA_OFF(s)   (33792 + (s) * 3880)
#define RIB_IN      41552
#define RIB_OUT     43492
#define HA_OFF(s)   (33792 + (s) * 1920)
#define HB_OFF(s)   (33792 + 3840 + (s) * 1280)
#define POOL_FLOATS 45412
#define SMEM_BYTES  (POOL_FLOATS * 4)

// ================== persistent mega kernel ==================
__global__ void __launch_bounds__(NTHR, 1) mega_kernel(
    const float* __restrict__ feats, const float* __restrict__ Wd,
    const float* __restrict__ bd,
    const float* __restrict__ Wl, const float* __restrict__ Wr,
    const float* __restrict__ Gl, const float* __restrict__ Gr,
    const float* __restrict__ bl, const float* __restrict__ br,
    const float* __restrict__ bgl, const float* __restrict__ bgr,
    const float* __restrict__ Wt, const float* __restrict__ bt,
    const float* __restrict__ trans, const int* __restrict__ tags,
    float* __restrict__ out)
{
    extern __shared__ __align__(16) float pool[];
    const int cta = blockIdx.x;
    const int tid = threadIdx.x;
    const int lane = tid & 31, warp = tid >> 5;
    const int g = lane >> 2, c = lane & 3;

    // ================= phase 0a: zero g_ex, build g_biasS =================
    for (int i = cta * NTHR + tid; i < L * NT * SPAN; i += NCTA * NTHR) g_ex[i] = 0.f;
    if (cta == 0) {
        for (int i = tid; i < 1024; i += NTHR) {
            int dd = i >> 2, jj = i & 3;
            g_biasS[i] = (jj == 0) ? (bl[dd] + br[dd])
                                   : (bgl[(jj - 1) * 256 + dd] + bgr[(jj - 1) * 256 + dd]);
        }
    }

    // ================= phase 0b: h = feats @ Wd^T + bd  (BM=48, BN=32, all CTAs) ===
    {
        const int m0h = (cta >> 3) * 48, n0h = (cta & 7) * 32;
        const int wmh = warp >> 2, wnh = warp & 3;       // 0..2, 0..3
        const int har = tid >> 3, hac = (tid & 7) * 4;   // 384 A f4 chunks
        const bool do_b = tid < 256;
        float acch[4] = {};

        cpa16(&pool[HA_OFF(0) + har * 40 + hac], &feats[(size_t)(m0h + har) * 512 + hac]);
        if (do_b) cpa16(&pool[HB_OFF(0) + har * 40 + hac], &Wd[(size_t)(n0h + har) * 512 + hac]);
        CP_COMMIT();

#pragma unroll
        for (int step = 0; step < 16; step++) {
            const int s = step & 1;
            CP_WAIT(0);
            __syncthreads();
            if (step + 1 < 16) {
                const int k0 = (step + 1) * 32, s2 = s ^ 1;
                cpa16(&pool[HA_OFF(s2) + har * 40 + hac],
                      &feats[(size_t)(m0h + har) * 512 + k0 + hac]);
                if (do_b) cpa16(&pool[HB_OFF(s2) + har * 40 + hac],
                                &Wd[(size_t)(n0h + har) * 512 + k0 + hac]);
                CP_COMMIT();
            }
#pragma unroll
            for (int kc = 0; kc < 4; kc++) {
                const int ko = kc * 8 + 2 * c;
                const float* p = &pool[HA_OFF(s) + (wmh * 16 + g) * 40 + ko];
                float2 fa0 = *(const float2*)p;
                float2 fa1 = *(const float2*)(p + 8 * 40);
                const float* pb = &pool[HB_OFF(s) + (wnh * 8 + g) * 40 + ko];
                float2 fb = *(const float2*)pb;
                mma_tf32(acch[0], acch[1], acch[2], acch[3],
                         F2U(fa0.x), F2U(fa1.x), F2U(fa0.y), F2U(fa1.y),
                         F2U(fb.x), F2U(fb.y));
            }
        }
        {
            int col = n0h + wnh * 8 + 2 * c;
            int row0 = m0h + wmh * 16 + g;
            g_ht[0][(size_t)row0 * 256 + col]           = acch[0] + bd[col];
            g_ht[0][(size_t)row0 * 256 + col + 1]       = acch[1] + bd[col + 1];
            g_ht[0][(size_t)(row0 + 8) * 256 + col]     = acch[2] + bd[col];
            g_ht[0][(size_t)(row0 + 8) * 256 + col + 1] = acch[3] + bd[col + 1];
        }
    }

    // ================= phase 0c: load resident stacked B tile (once) =================
    const int n0 = (cta & 15) * 64;                      // dual-phase n tile
    {
        for (int ch = tid; ch < 2 * 64 * 64; ch += NTHR) {
            int half = ch >> 12;
            int rem = ch & 4095;
            int rowB = rem >> 6;
            int c4 = (rem & 63) * 4;
            int colp = n0 + rowB;
            int d = colp >> 2, j = colp & 3;
            const float* src = half ? ((j == 0) ? Wr : Gr) : ((j == 0) ? Wl : Gl);
            int srow = (j == 0) ? d : (j - 1) * 256 + d;
            *(float4*)&pool[half * BR_HALF + rowB * SB + c4] =
                *(const float4*)&src[(size_t)srow * 256 + c4];
        }
    }

    grid_bar();

    // ========== phase 1..7: fused dual GEMM + gate (B resident, SW-pipelined) =======
    {
        const int m0 = (cta >> 4) * 96;
        const int wm = warp >> 1, wn = warp & 1;         // 0..5, 0..1
        const int ar0 = tid >> 3,          ac0 = (tid & 7) * 4;
        const int ar1 = (tid + 384) >> 3,  ac1 = ((tid + 384) & 7) * 4;
        const int ar2 = (tid + 768) >> 3,  ac2 = ((tid + 768) & 7) * 4;   // tid<8
        const int q = cta & 15;                          // d0 = q*16
        const int qd = q >> 1;                           // capture step
        const int qoff = (q & 1) * 16;                   // col offset within stage

        // sl-invariant shared read bases
        const float* bbase[4][2];
#pragma unroll
        for (int ni = 0; ni < 4; ni++) {
            int rowB = wn * 32 + ni * 8 + g;
            bbase[ni][0] = pool + rowB * SB + 2 * c;
            bbase[ni][1] = pool + BR_HALF + rowB * SB + 2 * c;
        }
        const float* abase[2] = { pool + DA_OFF(0) + (wm * 16 + g) * 40 + 2 * c,
                                  pool + DA_OFF(1) + (wm * 16 + g) * 40 + 2 * c };
        // sl-invariant bias (g_biasS written by cta0 before grid_bar)
        float bpre[4][2];
#pragma unroll
        for (int ni = 0; ni < 4; ni++) {
            int colb = n0 + wn * 32 + ni * 8 + 2 * c;
            bpre[ni][0] = g_biasS[colb];
            bpre[ni][1] = g_biasS[colb + 1];
        }

        for (int sl = 1; sl <= 7; sl++) {
            const int M = L - sl;
            const float* Aht = g_ht[sl - 1];
            float* htout = g_ht[sl];
            float acc[4][4] = {};

            cpa16(&pool[DA_OFF(0) + ar0 * 40 + ac0], &Aht[(size_t)(m0 + ar0) * 256 + ac0]);
            cpa16(&pool[DA_OFF(0) + ar1 * 40 + ac1], &Aht[(size_t)(m0 + ar1) * 256 + ac1]);
            if (tid < 8)
                cpa16(&pool[DA_OFF(0) + ar2 * 40 + ac2], &Aht[(size_t)(m0 + ar2) * 256 + ac2]);
            CP_COMMIT();

#pragma unroll
            for (int step = 0; step < 8; step++) {
                const int s = step & 1;
                CP_WAIT(0);
                __syncthreads();
                if (step + 1 < 8) {
                    const int k0 = (step + 1) * 32, s2 = s ^ 1;
                    cpa16(&pool[DA_OFF(s2) + ar0 * 40 + ac0],
                          &Aht[(size_t)(m0 + ar0) * 256 + k0 + ac0]);
                    cpa16(&pool[DA_OFF(s2) + ar1 * 40 + ac1],
                          &Aht[(size_t)(m0 + ar1) * 256 + k0 + ac1]);
                    if (tid < 8)
                        cpa16(&pool[DA_OFF(s2) + ar2 * 40 + ac2],
                              &Aht[(size_t)(m0 + ar2) * 256 + k0 + ac2]);
                    CP_COMMIT();
                }
                // ---- ribbon capture: A columns [d0, d0+16) live in this stage ----
                if (step == qd) {
                    int rowl = tid >> 2, c4 = (tid & 3) * 4;
                    float4 v = *(const float4*)&pool[DA_OFF(s) + rowl * 40 + qoff + c4];
                    *(float4*)&pool[RIB_IN + rowl * 20 + c4] = v;
                    if (tid < 4) {
                        float4 w = *(const float4*)&pool[DA_OFF(s) + 96 * 40 + qoff + tid * 4];
                        *(float4*)&pool[RIB_IN + 96 * 20 + tid * 4] = w;
                    }
                }
                // ---- software-pipelined MMA body: B frags prefetched one kc ahead ----
                {
                    const float* ab = abase[s];
                    const int kgs = step * 32;
                    float2 bl0 = *(const float2*)(bbase[0][0] + kgs);
                    float2 br0 = *(const float2*)(bbase[0][1] + kgs);
                    float2 bl1 = *(const float2*)(bbase[1][0] + kgs);
                    float2 br1 = *(const float2*)(bbase[1][1] + kgs);
                    float2 bl2 = *(const float2*)(bbase[2][0] + kgs);
                    float2 br2 = *(const float2*)(bbase[2][1] + kgs);
                    float2 bl3 = *(const float2*)(bbase[3][0] + kgs);
                    float2 br3 = *(const float2*)(bbase[3][1] + kgs);
#pragma unroll
                    for (int kc = 0; kc < 4; kc++) {
                        const float* ap = ab + kc * 8;
                        float2 fa0 = *(const float2*)ap;
                        float2 fa1 = *(const float2*)(ap + 320);
                        float2 fr0 = *(const float2*)(ap + 40);
                        float2 fr1 = *(const float2*)(ap + 360);
                        float2 nl0, nr0, nl1, nr1, nl2, nr2, nl3, nr3;
                        if (kc < 3) {
                            const int kg = kgs + kc * 8 + 8;
                            nl0 = *(const float2*)(bbase[0][0] + kg);
                            nr0 = *(const float2*)(bbase[0][1] + kg);
                            nl1 = *(const float2*)(bbase[1][0] + kg);
                            nr1 = *(const float2*)(bbase[1][1] + kg);
                            nl2 = *(const float2*)(bbase[2][0] + kg);
                            nr2 = *(const float2*)(bbase[2][1] + kg);
                            nl3 = *(const float2*)(bbase[3][0] + kg);
                            nr3 = *(const float2*)(bbase[3][1] + kg);
                        }
                        uint32_t a0 = F2U(fa0.x), a1 = F2U(fa1.x),
                                 a2 = F2U(fa0.y), a3 = F2U(fa1.y);
                        uint32_t r0 = F2U(fr0.x), r1 = F2U(fr1.x),
                                 r2 = F2U(fr0.y), r3 = F2U(fr1.y);
                        mma_tf32(acc[0][0], acc[0][1], acc[0][2], acc[0][3],
                                 a0, a1, a2, a3, F2U(bl0.x), F2U(bl0.y));
                        mma_tf32(acc[0][0], acc[0][1], acc[0][2], acc[0][3],
                                 r0, r1, r2, r3, F2U(br0.x), F2U(br0.y));
                        mma_tf32(acc[1][0], acc[1][1], acc[1][2], acc[1][3],
                                 a0, a1, a2, a3, F2U(bl1.x), F2U(bl1.y));
                        mma_tf32(acc[1][0], acc[1][1], acc[1][2], acc[1][3],
                                 r0, r1, r2, r3, F2U(br1.x), F2U(br1.y));
                        mma_tf32(acc[2][0], acc[2][1], acc[2][2], acc[2][3],
                                 a0, a1, a2, a3, F2U(bl2.x), F2U(bl2.y));
                        mma_tf32(acc[2][0], acc[2][1], acc[2][2], acc[2][3],
                                 r0, r1, r2, r3, F2U(br2.x), F2U(br2.y));
                        mma_tf32(acc[3][0], acc[3][1], acc[3][2], acc[3][3],
                                 a0, a1, a2, a3, F2U(bl3.x), F2U(bl3.y));
                        mma_tf32(acc[3][0], acc[3][1], acc[3][2], acc[3][3],
                                 r0, r1, r2, r3, F2U(br3.x), F2U(br3.y));
                        if (kc < 3) {
                            bl0 = nl0; br0 = nr0; bl1 = nl1; br1 = nr1;
                            bl2 = nl2; br2 = nr2; bl3 = nl3; br3 = nr3;
                        }
                    }
                }
            }
            __syncthreads();           // rib_in complete (covers qd==7 case)

            // ---- fused gate epilogue: smem in, smem out ----
#pragma unroll
            for (int ni = 0; ni < 4; ni++) {
                float z00 = acc[ni][0] + bpre[ni][0], z01 = acc[ni][1] + bpre[ni][1];
                float z10 = acc[ni][2] + bpre[ni][0], z11 = acc[ni][3] + bpre[ni][1];
                float w00 = __shfl_xor_sync(0xffffffffu, z00, 1);
                float w01 = __shfl_xor_sync(0xffffffffu, z01, 1);
                float w10 = __shfl_xor_sync(0xffffffffu, z10, 1);
                float w11 = __shfl_xor_sync(0xffffffffu, z11, 1);
                if ((c & 1) == 0) {
                    int dl = wn * 8 + ni * 2 + (c >> 1);
                    int rowl0 = wm * 16 + g;
#pragma unroll
                    for (int rr = 0; rr < 2; rr++) {
                        int rowl = rowl0 + rr * 8;
                        float zh  = rr ? z10 : z00;
                        float zg0 = rr ? z11 : z01;
                        float zg1 = rr ? w10 : w00;
                        float zg2 = rr ? w11 : w01;
                        float lft = pool[RIB_IN + rowl * 20 + dl];
                        float rgt = pool[RIB_IN + (rowl + 1) * 20 + dl];
                        float hh = 4.f / (1.f + __expf(-zh)) - 2.f;
                        float mx = fmaxf(zg0, fmaxf(zg1, zg2));
                        float e0 = __expf(zg0 - mx), e1 = __expf(zg1 - mx),
                              e2 = __expf(zg2 - mx);
                        float inv = 1.f / (e0 + e1 + e2);
                        pool[RIB_OUT + rowl * 20 + dl] =
                            (e0 * hh + e1 * lft + e2 * rgt) * inv;
                    }
                }
            }
            __syncthreads();
            // ---- coalesced store of the 96x16 output ribbon ----
            {
                int rowl = tid >> 2, c4 = (tid & 3) * 4;
                if (m0 + rowl < M) {
                    float4 v = *(const float4*)&pool[RIB_OUT + rowl * 20 + c4];
                    *(float4*)&htout[(size_t)(m0 + rowl) * 256 + q * 16 + c4] = v;
                }
            }
            grid_bar();
        }
    }

    // ================= phase 8: tag scores + exp gather (B region dead) =============
    {
        for (int i = tid; i < NT * D; i += NTHR) pool[i] = Wt[i];
        __syncthreads();
#pragma unroll
        for (int rep = 0; rep < 4; rep++) {
            int gw = cta * 12 + warp + rep * 1536;       // 0..6143
            int sl = gw / L;
            int pos = gw - sl * L;
            if (pos + sl < L) {
                const float* hp = g_ht[sl] + (size_t)pos * D;
                float4 h0 = *(const float4*)&hp[lane * 8];
                float4 h1 = *(const float4*)&hp[lane * 8 + 4];
                float hv[8] = {h0.x,h0.y,h0.z,h0.w,h1.x,h1.y,h1.z,h1.w};
                int i_end = pos + sl, kk = 7 - sl;
#pragma unroll
                for (int t = 0; t < NT; t++) {
                    const float* wp = &pool[t * D + lane * 8];
                    float4 w0 = *(const float4*)wp;
                    float4 w1 = *(const float4*)(wp + 4);
                    float s = hv[0]*w0.x + hv[1]*w0.y + hv[2]*w0.z + hv[3]*w0.w
                            + hv[4]*w1.x + hv[5]*w1.y + hv[6]*w1.z + hv[7]*w1.w;
#pragma unroll
                    for (int o = 16; o; o >>= 1) s += __shfl_xor_sync(0xffffffffu, s, o);
                    if (lane == 0) {
                        float val = s + bt[t];
                        g_tagsc[sl][pos * NT + t] = val;
                        g_ex[((size_t)i_end * NT + t) * SPAN + kk] = __expf(val);
                    }
                }
            }
        }
    }

    grid_bar();

    // ================= phase 9: chunk transfer matrices (128*9 = 1152 runs) ==========
    if (warp < 9) {
        const int run = cta * 9 + warp;
        const int chunk = run / 96, j = run - chunk * 96;
        const int slotj = j / 12, tj = j - slotj * 12;
        const int t2 = (lane < 12) ? lane : 11;

        float eTc[12];
#pragma unroll
        for (int t1 = 0; t1 < 12; t1++) eTc[t1] = __expf(trans[t1 * 12 + t2]);

        float Cw[8];
#pragma unroll
        for (int k = 0; k < 8; k++) Cw[k] = 0.f;
        if (lane == tj) Cw[slotj] = 1.f;
        float sc = 0.f;
        float lastA = 0.f;

        const float4* exb = (const float4*)(g_ex + ((size_t)(chunk * 64) * 12 + t2) * 8);
        float4 c0 = exb[0], c1 = exb[1];
        float4 n0v = exb[24], n1v = exb[25];

        for (int blk = 0; blk < 8; blk++) {
#pragma unroll
            for (int u = 0; u < 8; u++) {
                const int li = blk * 8 + u;
                float4 f0 = c0, f1 = c1;
                c0 = n0v; c1 = n1v;
                if (li + 2 < 64) {
                    n0v = exb[(li + 2) * 24];
                    n1v = exb[(li + 2) * 24 + 1];
                }
                float e0=f0.x,e1=f0.y,e2=f0.z,e3=f0.w,e4=f1.x,e5=f1.y,e6=f1.z,e7=f1.w;
                float v01 = fmaf(e1, Cw[(u + 1) & 7], e0 * Cw[(u + 0) & 7]);
                float v23 = fmaf(e3, Cw[(u + 3) & 7], e2 * Cw[(u + 2) & 7]);
                float v45 = fmaf(e5, Cw[(u + 5) & 7], e4 * Cw[(u + 4) & 7]);
                float v6  = e6 * Cw[(u + 6) & 7];
                float A = fmaf(e7, Cw[(u + 7) & 7], (v01 + v23) + (v45 + v6));
                lastA = A;
                float bnA = 0.f, bnB = 0.f;
#pragma unroll
                for (int t1 = 0; t1 < 6; t1++) {
                    bnA = fmaf(eTc[t1],     __shfl_sync(0xffffffffu, A, t1),     bnA);
                    bnB = fmaf(eTc[t1 + 6], __shfl_sync(0xffffffffu, A, t1 + 6), bnB);
                }
                Cw[u] = bnA + bnB;
            }
            if (blk != 7) {
                float m = (lane < 12) ? Cw[7] : 0.f;
#pragma unroll
                for (int o = 16; o; o >>= 1) m = fmaxf(m, __shfl_xor_sync(0xffffffffu, m, o));
                if (m < 1e-30f) m = 1.f;
                float inv = 1.f / m;
#pragma unroll
                for (int k = 0; k < 8; k++) Cw[k] *= inv;
                sc += __logf(m);
            }
        }

        if (chunk < 11) {
            if (lane < 12) {
#pragma unroll
                for (int slot = 0; slot < 8; slot++)
                    g_GT[((size_t)chunk * 96 + j) * 96 + slot * 12 + lane] = Cw[slot];
            }
            if (lane == 0) g_sc[chunk * 96 + j] = sc;
        } else {
            if (lane < 12) g_R[j * 12 + lane] = lastA;
            if (lane == 0) g_sc[11 * 96 + j] = sc;
        }
    }

    grid_bar();
    if (cta != 0) return;

    // ================= phase 10 (CTA 0 only): gold + chunk matvec chain ==============
    {
        float* s_sh   = pool;            // 96
        float* st_sh  = pool + 96;       // 96
        float* lv     = pool + 192;      // 11
        float* wred   = pool + 204;      // 3
        float* wred2  = pool + 208;      // 3
        float* gold_sh= pool + 212;      // 1
        float* scall  = pool + 256;      // 1152
        float* Rsh    = pool + 1472;     // 1152
        float* part   = pool + 2688;     // 768

        __syncthreads();
        for (int i = tid; i < 1152; i += NTHR) { scall[i] = g_sc[i]; Rsh[i] = g_R[i]; }

        if (warp == 0) {
            float gold = 0.f;
            for (int s = lane; s < 96; s += 32) {
                int i  = tags[s * 4 + 0];
                int j  = tags[s * 4 + 1];
                int pr = tags[s * 4 + 2];
                int t  = tags[s * 4 + 3];
                int sl = j - i;
                float base = (sl >= 0 && sl < SPAN && i >= 0 && i + sl < L)
                           ? g_tagsc[sl][i * NT + t] : bt[t];
                gold += base + trans[pr * NT + t];
            }
#pragma unroll
            for (int o = 16; o; o >>= 1) gold += __shfl_xor_sync(0xffffffffu, gold, o);
            if (lane == 0) gold_sh[0] = gold;
        }
        if (tid < 96) s_sh[tid] = (tid >= 84) ? expf(trans[10 * 12 + (tid - 84)]) : 0.f;
        __syncthreads();

        float Sacc = 0.f, mc = 0.f;
        for (int cch = 0; cch < 12; cch++) {
            float m = (tid < 96) ? scall[cch * 96 + tid] : -3e38f;
#pragma unroll
            for (int off = 16; off; off >>= 1) m = fmaxf(m, __shfl_xor_sync(0xffffffffu, m, off));
            if (tid < 96 && lane == 0) wred[warp] = m;
            __syncthreads();
            mc = fmaxf(fmaxf(wred[0], wred[1]), wred[2]);
            if (tid < 96) st_sh[tid] = s_sh[tid] * expf(scall[cch * 96 + tid] - mc);
            __syncthreads();

            if (cch < 11) {
                if (warp < 8) {
                    const float* G = g_GT + (size_t)cch * 9216 + (size_t)(warp * 12) * 96;
                    const float* sv = &st_sh[warp * 12];
                    float a0 = 0.f, a1 = 0.f, a2 = 0.f;
#pragma unroll
                    for (int j = 0; j < 12; j++) {
                        float svj = sv[j];
                        a0 = fmaf(G[j * 96 + lane],      svj, a0);
                        a1 = fmaf(G[j * 96 + lane + 32], svj, a1);
                        a2 = fmaf(G[j * 96 + lane + 64], svj, a2);
                    }
                    part[warp * 96 + lane]      = a0;
                    part[warp * 96 + lane + 32] = a1;
                    part[warp * 96 + lane + 64] = a2;
                }
                __syncthreads();
                float snew = 0.f;
                if (tid < 96) {
                    snew = ((part[tid] + part[96 + tid]) + (part[192 + tid] + part[288 + tid]))
                         + ((part[384 + tid] + part[480 + tid]) + (part[576 + tid] + part[672 + tid]));
                }
                float m2 = (tid < 96) ? snew : 0.f;
#pragma unroll
                for (int off = 16; off; off >>= 1) m2 = fmaxf(m2, __shfl_xor_sync(0xffffffffu, m2, off));
                if (tid < 96 && lane == 0) wred2[warp] = m2;
                __syncthreads();
                float mx = fmaxf(fmaxf(wred2[0], wred2[1]), wred2[2]);
                if (mx < 1e-30f) mx = 1.f;
                if (tid < 96) s_sh[tid] = snew / mx;
                Sacc += mc + logf(mx);
                __syncthreads();
            }
        }

        if (tid < 11) {
            float a0 = 0.f, a1 = 0.f, a2 = 0.f, a3 = 0.f;
#pragma unroll 4
            for (int j = 0; j < 96; j += 4) {
                a0 = fmaf(Rsh[(j + 0) * 12 + tid], st_sh[j + 0], a0);
                a1 = fmaf(Rsh[(j + 1) * 12 + tid], st_sh[j + 1], a1);
                a2 = fmaf(Rsh[(j + 2) * 12 + tid], st_sh[j + 2], a2);
                a3 = fmaf(Rsh[(j + 3) * 12 + tid], st_sh[j + 3], a3);
            }
            lv[tid] = logf((a0 + a1) + (a2 + a3));
        }
        __syncthreads();
        if (tid == 0) {
            float logZ = 11.f * (Sacc + mc);
            for (int t = 0; t < 11; t++) logZ += lv[t];
            out[0] = logZ - gold_sh[0];
        }
    }
}

// ---------------- launch ----------------
extern "C" void kernel_launch(void* const* d_in, const int* in_sizes, int n_in,
                              void* d_out, int out_size)
{
    const float* feats = (const float*)d_in[0];
    const int*   tags  = (const int*)d_in[1];
    const float* Wd    = (const float*)d_in[2];
    const float* bd    = (const float*)d_in[3];
    const float* Wl    = (const float*)d_in[4];
    const float* bl    = (const float*)d_in[5];
    const float* Wr    = (const float*)d_in[6];
    const float* br    = (const float*)d_in[7];
    const float* Gl    = (const float*)d_in[8];
    const float* bgl   = (const float*)d_in[9];
    const float* Gr    = (const float*)d_in[10];
    const float* bgr   = (const float*)d_in[11];
    const float* Wt    = (const float*)d_in[12];
    const float* bt    = (const float*)d_in[13];
    const float* trans = (const float*)d_in[14];
    float* out = (float*)d_out;

    cudaFuncSetAttribute(mega_kernel, cudaFuncAttributeMaxDynamicSharedMemorySize,
                         SMEM_BYTES);
    mega_kernel<<<NCTA, NTHR, SMEM_BYTES>>>(feats, Wd, bd, Wl, Wr, Gl, Gr,
                                            bl, br, bgl, bgr, Wt, bt, trans, tags, out);
}